// round 3
// baseline (speedup 1.0000x reference)
#include <cuda_runtime.h>
#include <math.h>

#define NN  1000
#define HH  128
#define MM  128
#define HM  256
#define DEG 16
#define MAXSTEPS 10000
#define CAPQ (NN + MAXSTEPS*DEG + 64)

// Persistent scratch (device globals; no allocation allowed)
__device__ float g_feats[NN*HH];        // latest state per node
__device__ int   g_qn  [CAPQ];          // queue: node id
__device__ int   g_qmid[CAPQ];          // queue: message event id (-1 => first_message[node])
__device__ float g_qmsg[MAXSTEPS*MM];   // one 128-float message per processed event

struct __align__(16) SimSmem {
  float nsw[HM*HH];   // ns_w in (r/4, col, r%4) float4 layout
  float x[HM];        // [feats(128), msg(128)]
  float b[HM];        // [ns(128),    msg(128)]
  float part[512];
  float actw[HM];
  float nsb[HH];
  float nmb[HH];
  float g[HH];        // running graph readout (sum over nodes of final)
  float red[8];
  float tact[NN];
  float newact;
  float actb;
  int head, tail, pops, ev, node, mid, found;
};

__global__ void enc_kernel(const float* __restrict__ xa,
                           const float* __restrict__ enc_w,
                           const float* __restrict__ enc_b) {
  int n = blockIdx.x, h = threadIdx.x;
  float a = enc_b[h];
  #pragma unroll
  for (int k = 0; k < 32; k++) a = fmaf(xa[n*32 + k], enc_w[k*HH + h], a);
  g_feats[n*HH + h] = a;
}

__global__ __launch_bounds__(512, 1) void sim_kernel(
    const float* __restrict__ fm,   const int* __restrict__ nb,
    const int*   __restrict__ nsp,
    const float* __restrict__ ns_w, const float* __restrict__ ns_b,
    const float* __restrict__ nm_w, const float* __restrict__ nm_b,
    const float* __restrict__ act_w, const float* __restrict__ act_b,
    const float* __restrict__ dec_w, const float* __restrict__ dec_b,
    float* __restrict__ out)
{
  extern __shared__ char raw[];
  SimSmem* s = (SimSmem*)raw;
  const int tid = threadIdx.x;
  const int col = tid & 127;
  const int q   = tid >> 7;
  const float THRESH = 1.0f - 1e-7f;

  // nm_w: 64 fp32 weights per thread, register-resident.
  // thread (q,col) owns rows q*64..q*64+63 of column `col`.
  float wreg[64];
  #pragma unroll
  for (int j = 0; j < 64; j++) wreg[j] = nm_w[(q*64 + j)*HH + col];

  // ns_w into smem: pack 4 consecutive rows per float4 so the GEMV uses
  // conflict-free LDS.128 (lanes differ in col -> 16B apart).
  for (int i = tid; i < HM*HH; i += 512) {
    int r = i / HH, c = i % HH;
    s->nsw[(((r >> 2)*HH + c) << 2) + (r & 3)] = ns_w[i];
  }
  for (int i = tid; i < HM; i += 512) s->actw[i] = act_w[i];
  for (int i = tid; i < HH; i += 512) { s->nsb[i] = ns_b[i]; s->nmb[i] = nm_b[i]; s->g[i] = 0.f; }
  for (int i = tid; i < NN; i += 512) s->tact[i] = 0.f;
  if (tid == 0) {
    int nst = nsp ? nsp[0] : 64;
    s->head = 0; s->tail = nst; s->pops = 0; s->ev = 0;
    s->actb = act_b[0];
  }
  __syncthreads();
  int nstart = s->tail;
  for (int i = tid; i < nstart; i += 512) { g_qn[i] = i; g_qmid[i] = -1; }
  __syncthreads();

  while (true) {
    // ---- scan: skip halted pops in batches of 32 (tact monotone => sound) ----
    if (tid < 32) {
      int head = s->head, tail = s->tail, pops = s->pops;
      if (pops >= MAXSTEPS || head >= tail) {
        if (tid == 0) s->found = -1;
      } else {
        int L = min(32, min(tail - head, MAXSTEPS - pops));
        bool ok = tid < L;
        int idx = head + (ok ? tid : 0);
        int nd = g_qn[idx];
        int md = g_qmid[idx];
        bool live = ok && (s->tact[nd] <= THRESH);
        unsigned mask = __ballot_sync(0xffffffffu, live);
        if (mask) {
          int d = __ffs(mask) - 1;
          int nd_d = __shfl_sync(0xffffffffu, nd, d);
          int md_d = __shfl_sync(0xffffffffu, md, d);
          if (tid == 0) {
            s->node = nd_d; s->mid = md_d;
            s->head = head + d + 1; s->pops = pops + d + 1; s->found = 1;
          }
        } else {
          if (tid == 0) { s->head = head + L; s->pops = pops + L; s->found = 0; }
        }
      }
    }
    __syncthreads();
    int f = s->found;
    if (f < 0) break;       // done (step budget exhausted or queue empty)
    if (f == 0) continue;   // whole batch halted; scan next batch

    const int node = s->node;
    const int mid  = s->mid;

    // ---- gather x = [feats[node], msg] ----
    if (tid < HH) {
      s->x[tid] = g_feats[node*HH + tid];
    } else if (tid < HM) {
      int j = tid - HH;
      s->x[tid] = (mid < 0) ? fm[node*MM + j] : g_qmsg[mid*MM + j];
    }
    __syncthreads();

    // ---- ACT partial (warps 0-7) + ns GEMV partial (all 512 threads) ----
    if (tid < HM) {
      float ap = s->x[tid] * s->actw[tid];
      #pragma unroll
      for (int o = 16; o > 0; o >>= 1) ap += __shfl_down_sync(0xffffffffu, ap, o);
      if ((tid & 31) == 0) s->red[tid >> 5] = ap;
    }
    {
      float acc = 0.f;
      const float4* wp = ((const float4*)s->nsw) + (q*16)*HH + col;
      const float4* xp = ((const float4*)s->x) + q*16;
      #pragma unroll
      for (int jj = 0; jj < 16; jj++) {
        float4 w = wp[jj*HH];
        float4 v = xp[jj];
        acc = fmaf(w.x, v.x, acc); acc = fmaf(w.y, v.y, acc);
        acc = fmaf(w.z, v.z, acc); acc = fmaf(w.w, v.w, acc);
      }
      s->part[tid] = acc;
    }
    __syncthreads();

    // ---- finalize ACT (thread 0) + finalize ns/relu (threads<128) ----
    if (tid == 0) {
      float z = s->red[0] + s->red[1] + s->red[2] + s->red[3]
              + s->red[4] + s->red[5] + s->red[6] + s->red[7] + s->actb;
      float cand = 1.0f / (1.0f + expf(-z));
      float ta = s->tact[node];
      float na = (ta + cand > 1.0f) ? (1.0f - ta) : cand;   // exact ref clamp
      s->tact[node] = ta + na;
      s->newact = na;
    }
    if (tid < HH) {
      float v = s->part[tid] + s->part[HH + tid] + s->part[2*HH + tid]
              + s->part[3*HH + tid] + s->nsb[tid];
      v = fmaxf(v, 0.f);
      s->b[tid] = v;
      g_feats[node*HH + tid] = v;          // feats update (proc is always true here)
    } else if (tid < HM) {
      s->b[tid] = s->x[tid];               // msg half of [ns, msg]
    }
    int myev = s->ev, mytail = s->tail;    // stable in this phase
    __syncthreads();

    // ---- g += ns*new_act ; nm GEMV partial (register weights) ----
    if (tid < HH) s->g[tid] += s->b[tid] * s->newact;
    {
      float acc = 0.f;
      const float4* bp = ((const float4*)s->b) + q*16;
      #pragma unroll
      for (int jj = 0; jj < 16; jj++) {
        float4 v = bp[jj];
        acc = fmaf(wreg[jj*4 + 0], v.x, acc);
        acc = fmaf(wreg[jj*4 + 1], v.y, acc);
        acc = fmaf(wreg[jj*4 + 2], v.z, acc);
        acc = fmaf(wreg[jj*4 + 3], v.w, acc);
      }
      s->part[tid] = acc;
    }
    __syncthreads();

    // ---- finalize nm, store event, enqueue 16 neighbor refs ----
    if (tid < HH) {
      float v = s->part[tid] + s->part[HH + tid] + s->part[2*HH + tid]
              + s->part[3*HH + tid] + s->nmb[tid];
      g_qmsg[myev*MM + tid] = v;
    }
    if (tid < DEG) {
      g_qn  [mytail + tid] = nb[node*DEG + tid];
      g_qmid[mytail + tid] = myev;
    }
    if (tid == 0) { s->ev = myev + 1; s->tail = mytail + DEG; }
    __syncthreads();
  }

  // ---- readout: logits = g @ dec_w + dec_b; log_softmax over OUT ----
  if (tid < 20) {
    int p = tid / 10, o = tid % 10;
    float a = dec_b[p*10 + o];
    for (int h = 0; h < HH; h++) a = fmaf(s->g[h], dec_w[(p*HH + h)*10 + o], a);
    s->part[tid] = a;
  }
  __syncthreads();
  if (tid < 2) {
    float mx = -1e30f;
    for (int o = 0; o < 10; o++) mx = fmaxf(mx, s->part[tid*10 + o]);
    float sum = 0.f;
    for (int o = 0; o < 10; o++) sum += expf(s->part[tid*10 + o] - mx);
    float lse = mx + logf(sum);
    for (int o = 0; o < 10; o++) out[tid*10 + o] = s->part[tid*10 + o] - lse;
  }
}

extern "C" void kernel_launch(void* const* d_in, const int* in_sizes, int n_in,
                              void* d_out, int out_size) {
  (void)out_size;
  const float* xa = (const float*)d_in[0];
  const float* fm = (const float*)d_in[1];
  const int*   nb = (const int*)d_in[2];
  const int*   nsp = nullptr;
  int b = 3;
  if (n_in >= 14 && in_sizes[3] == 1) { nsp = (const int*)d_in[3]; b = 4; }
  const float* enc_w = (const float*)d_in[b + 0];
  const float* enc_b = (const float*)d_in[b + 1];
  const float* ns_w  = (const float*)d_in[b + 2];
  const float* ns_b  = (const float*)d_in[b + 3];
  const float* nm_w  = (const float*)d_in[b + 4];
  const float* nm_b  = (const float*)d_in[b + 5];
  const float* act_w = (const float*)d_in[b + 6];
  const float* act_b = (const float*)d_in[b + 7];
  const float* dec_w = (const float*)d_in[b + 8];
  const float* dec_b = (const float*)d_in[b + 9];

  enc_kernel<<<NN, HH>>>(xa, enc_w, enc_b);

  cudaFuncSetAttribute(sim_kernel, cudaFuncAttributeMaxDynamicSharedMemorySize,
                       (int)sizeof(SimSmem));
  sim_kernel<<<1, 512, sizeof(SimSmem)>>>(fm, nb, nsp, ns_w, ns_b, nm_w, nm_b,
                                          act_w, act_b, dec_w, dec_b,
                                          (float*)d_out);
}

// round 4
// speedup vs baseline: 1.7338x; 1.7338x over previous
#include <cuda_runtime.h>
#include <math.h>

#define NN  1000
#define HH  128
#define MM  128
#define HM  256
#define DEG 16
#define MAXSTEPS 10000
#define CAPQ (NN + MAXSTEPS*DEG + 64)
#define BMAX 8
#define SCANW 64

// Persistent device scratch (no allocation allowed)
__device__ float g_feats[NN*HH];
__device__ int   g_qn  [CAPQ];
__device__ int   g_qmid[CAPQ];           // -1 => first_message[node]
__device__ float g_qmsg[MAXSTEPS*MM];
// weights packed as float4 of 4 consecutive rows at fixed col: idx (r>>2)*128+col
__device__ ulonglong2 g_nswp[8192];      // 128 KB
__device__ ulonglong2 g_nmwp[8192];      // 128 KB

__device__ __forceinline__ unsigned long long fma2(unsigned long long a,
                                                   unsigned long long b,
                                                   unsigned long long c) {
  unsigned long long d;
  asm("fma.rn.f32x2 %0, %1, %2, %3;" : "=l"(d) : "l"(a), "l"(b), "l"(c));
  return d;
}
__device__ __forceinline__ float unpack_add(unsigned long long a) {
  float lo, hi;
  asm("mov.b64 {%0,%1}, %2;" : "=f"(lo), "=f"(hi) : "l"(a));
  return lo + hi;
}

__global__ void enc_kernel(const float* __restrict__ xa,
                           const float* __restrict__ enc_w,
                           const float* __restrict__ enc_b) {
  int n = blockIdx.x, h = threadIdx.x;
  float a = enc_b[h];
  #pragma unroll
  for (int k = 0; k < 32; k++) a = fmaf(xa[n*32 + k], enc_w[k*HH + h], a);
  g_feats[n*HH + h] = a;
}

__global__ void pack_kernel(const float* __restrict__ ns_w,
                            const float* __restrict__ nm_w) {
  int r = blockIdx.x, c = threadIdx.x;
  int dst = (((r >> 2)*HH + c) << 2) + (r & 3);
  ((float*)g_nswp)[dst] = ns_w[r*HH + c];
  ((float*)g_nmwp)[dst] = nm_w[r*HH + c];
}

__global__ __launch_bounds__(512, 1) void sim_kernel(
    const float* __restrict__ fm,   const int* __restrict__ nb,
    const int*   __restrict__ nsp,
    const float* __restrict__ ns_b, const float* __restrict__ nm_b,
    const float* __restrict__ act_w, const float* __restrict__ act_b,
    const float* __restrict__ dec_w, const float* __restrict__ dec_b,
    float* __restrict__ out)
{
  __shared__ __align__(16) float s_x[BMAX][HM];    // batch inputs [feats,msg]
  __shared__ __align__(16) float s_b[BMAX][HM];    // [ns, msg]
  __shared__ float s_part[BMAX*4*HH];              // GEMM partials
  __shared__ float s_actw[HM];
  __shared__ float s_nsb[HH], s_nmb[HH], s_g[HH];
  __shared__ float s_tact[NN];
  __shared__ float s_na[BMAX];
  __shared__ int   s_scanNd[SCANW], s_scanMid[SCANW], s_scanLive[SCANW];
  __shared__ int   s_bn[BMAX], s_bmid[BMAX];
  __shared__ int   s_head, s_tail, s_pops, s_ev, s_bcnt, s_done;
  __shared__ float s_actb;

  const int tid = threadIdx.x;
  const int col = tid & 127;
  const int grp = tid >> 7;          // 0..3 -> rows grp*64 .. grp*64+63
  const int wid = tid >> 5;
  const int lid = tid & 31;
  const float THRESH = 1.0f - 1e-7f;

  for (int i = tid; i < HM; i += 512) s_actw[i] = act_w[i];
  for (int i = tid; i < HH; i += 512) { s_nsb[i] = ns_b[i]; s_nmb[i] = nm_b[i]; s_g[i] = 0.f; }
  for (int i = tid; i < NN; i += 512) s_tact[i] = 0.f;
  if (tid == 0) {
    int nst = nsp ? nsp[0] : 64;
    s_head = 0; s_tail = nst; s_pops = 0; s_ev = 0; s_done = 0;
    s_actb = act_b[0];
  }
  __syncthreads();
  int nstart = s_tail;
  for (int i = tid; i < nstart; i += 512) { g_qn[i] = i; g_qmid[i] = -1; }
  __syncthreads();

  while (true) {
    // ---- A: parallel preload of up to SCANW queue entries ----
    {
      int head = s_head, tail = s_tail, pops = s_pops;
      int L = min(SCANW, min(tail - head, MAXSTEPS - pops));
      if (tid < SCANW && tid < L) {
        int nd = g_qn[head + tid];
        s_scanNd[tid] = nd;
        s_scanMid[tid] = g_qmid[head + tid];
        s_scanLive[tid] = (s_tact[nd] <= THRESH) ? 1 : 0;
      }
    }
    __syncthreads();

    // ---- B: serial batch selection (thread 0) ----
    if (tid == 0) {
      int head = s_head, tail = s_tail, pops = s_pops;
      int L = min(SCANW, min(tail - head, MAXSTEPS - pops));
      if (L <= 0) { s_done = 1; s_bcnt = 0; }
      else {
        int bcnt = 0, k = 0;
        while (k < L && bcnt < BMAX) {
          if (!s_scanLive[k]) { k++; continue; }
          int nd = s_scanNd[k];
          bool dup = false;
          #pragma unroll
          for (int t = 0; t < BMAX; t++) if (t < bcnt && s_bn[t] == nd) dup = true;
          if (dup) break;
          s_bn[bcnt] = nd; s_bmid[bcnt] = s_scanMid[k];
          bcnt++; k++;
        }
        s_head = head + k; s_pops = pops + k; s_bcnt = bcnt;
      }
    }
    __syncthreads();
    if (s_done) break;
    const int bcnt = s_bcnt;
    if (bcnt == 0) continue;

    // ---- C: prefetch ns weights into regs + gather batch inputs ----
    ulonglong2 wv[16];
    #pragma unroll
    for (int jj = 0; jj < 16; jj++) wv[jj] = g_nswp[(grp*16 + jj)*HH + col];
    for (int i = tid; i < bcnt*HM; i += 512) {
      int j = i >> 8, k = i & 255;
      int nd = s_bn[j];
      float v;
      if (k < HH) v = g_feats[nd*HH + k];
      else {
        int md = s_bmid[j];
        v = (md < 0) ? fm[nd*MM + (k - HH)] : g_qmsg[md*MM + (k - HH)];
        s_b[j][k] = v;                   // msg half of [ns,msg]
      }
      s_x[j][k] = v;
    }
    __syncthreads();

    // ---- D: ACT (warps 0..bcnt-1) + ns GEMM (all threads) ----
    if (wid < bcnt) {
      float ap = 0.f;
      #pragma unroll
      for (int t = 0; t < 8; t++)
        ap = fmaf(s_x[wid][lid*8 + t], s_actw[lid*8 + t], ap);
      #pragma unroll
      for (int o = 16; o > 0; o >>= 1) ap += __shfl_down_sync(0xffffffffu, ap, o);
      if (lid == 0) {
        float z = ap + s_actb;
        float cand = 1.0f / (1.0f + expf(-z));
        int nd = s_bn[wid];
        float ta = s_tact[nd];
        float na = (ta + cand > 1.0f) ? (1.0f - ta) : cand;
        s_tact[nd] = ta + na;
        s_na[wid] = na;
      }
    }
    for (int j = 0; j < bcnt; j++) {
      const ulonglong2* xp = (const ulonglong2*)(s_x[j] + grp*64);
      unsigned long long acc = 0ULL;
      #pragma unroll
      for (int jj = 0; jj < 16; jj++) {
        ulonglong2 v = xp[jj];
        acc = fma2(wv[jj].x, v.x, acc);
        acc = fma2(wv[jj].y, v.y, acc);
      }
      s_part[(j*4 + grp)*HH + col] = unpack_add(acc);
    }
    __syncthreads();

    // ---- E: ns finalize (relu, feats, s_b) + prefetch nm weights ----
    #pragma unroll
    for (int jj = 0; jj < 16; jj++) wv[jj] = g_nmwp[(grp*16 + jj)*HH + col];
    for (int i = tid; i < bcnt*HH; i += 512) {
      int j = i >> 7, k = i & 127;
      float v = s_part[(j*4 + 0)*HH + k] + s_part[(j*4 + 1)*HH + k]
              + s_part[(j*4 + 2)*HH + k] + s_part[(j*4 + 3)*HH + k] + s_nsb[k];
      v = fmaxf(v, 0.f);
      s_b[j][k] = v;
      g_feats[s_bn[j]*HH + k] = v;
    }
    __syncthreads();

    // ---- F: g-accumulate + nm GEMM ----
    if (tid < HH) {
      float gv = s_g[tid];
      for (int j = 0; j < bcnt; j++) gv = fmaf(s_b[j][tid], s_na[j], gv);
      s_g[tid] = gv;
    }
    for (int j = 0; j < bcnt; j++) {
      const ulonglong2* bp = (const ulonglong2*)(s_b[j] + grp*64);
      unsigned long long acc = 0ULL;
      #pragma unroll
      for (int jj = 0; jj < 16; jj++) {
        ulonglong2 v = bp[jj];
        acc = fma2(wv[jj].x, v.x, acc);
        acc = fma2(wv[jj].y, v.y, acc);
      }
      s_part[(j*4 + grp)*HH + col] = unpack_add(acc);
    }
    __syncthreads();

    // ---- G: nm finalize -> event store + enqueue ----
    {
      int ev = s_ev, tail = s_tail;
      for (int i = tid; i < bcnt*HH; i += 512) {
        int j = i >> 7, k = i & 127;
        float v = s_part[(j*4 + 0)*HH + k] + s_part[(j*4 + 1)*HH + k]
                + s_part[(j*4 + 2)*HH + k] + s_part[(j*4 + 3)*HH + k] + s_nmb[k];
        g_qmsg[(ev + j)*MM + k] = v;
      }
      if (tid < bcnt*DEG) {
        int j = tid >> 4, d = tid & 15;
        g_qn  [tail + j*DEG + d] = nb[s_bn[j]*DEG + d];
        g_qmid[tail + j*DEG + d] = ev + j;
      }
      if (tid == 0) { s_ev = ev + bcnt; s_tail = tail + bcnt*DEG; }
    }
    __syncthreads();
  }

  // ---- readout: logits = g @ dec_w + dec_b; log_softmax ----
  __syncthreads();
  if (tid < 20) {
    int p = tid / 10, o = tid % 10;
    float a = dec_b[p*10 + o];
    for (int h = 0; h < HH; h++) a = fmaf(s_g[h], dec_w[(p*HH + h)*10 + o], a);
    s_part[tid] = a;
  }
  __syncthreads();
  if (tid < 2) {
    float mx = -1e30f;
    for (int o = 0; o < 10; o++) mx = fmaxf(mx, s_part[tid*10 + o]);
    float sum = 0.f;
    for (int o = 0; o < 10; o++) sum += expf(s_part[tid*10 + o] - mx);
    float lse = mx + logf(sum);
    for (int o = 0; o < 10; o++) out[tid*10 + o] = s_part[tid*10 + o] - lse;
  }
}

extern "C" void kernel_launch(void* const* d_in, const int* in_sizes, int n_in,
                              void* d_out, int out_size) {
  (void)out_size;
  const float* xa = (const float*)d_in[0];
  const float* fm = (const float*)d_in[1];
  const int*   nb = (const int*)d_in[2];
  const int*   nsp = nullptr;
  int b = 3;
  if (n_in >= 14 && in_sizes[3] == 1) { nsp = (const int*)d_in[3]; b = 4; }
  const float* enc_w = (const float*)d_in[b + 0];
  const float* enc_b = (const float*)d_in[b + 1];
  const float* ns_w  = (const float*)d_in[b + 2];
  const float* ns_b  = (const float*)d_in[b + 3];
  const float* nm_w  = (const float*)d_in[b + 4];
  const float* nm_b  = (const float*)d_in[b + 5];
  const float* act_w = (const float*)d_in[b + 6];
  const float* act_b = (const float*)d_in[b + 7];
  const float* dec_w = (const float*)d_in[b + 8];
  const float* dec_b = (const float*)d_in[b + 9];

  enc_kernel<<<NN, HH>>>(xa, enc_w, enc_b);
  pack_kernel<<<HM, HH>>>(ns_w, nm_w);
  sim_kernel<<<1, 512>>>(fm, nb, nsp, ns_b, nm_b, act_w, act_b,
                         dec_w, dec_b, (float*)d_out);
}

// round 5
// speedup vs baseline: 1.8492x; 1.0666x over previous
#include <cuda_runtime.h>
#include <math.h>

#define NN  1000
#define HH  128
#define MM  128
#define HM  256
#define DEG 16
#define MAXSTEPS 10000
#define CAPQ (NN + MAXSTEPS*DEG + 64)
#define BMAX 8
#define SCANW 64

// Persistent device scratch (no allocation allowed)
__device__ float g_feats[NN*HH];
__device__ int   g_qn  [CAPQ];
__device__ int   g_qmid[CAPQ];           // -1 => first_message[node]
__device__ float g_qmsg[MAXSTEPS*MM];
// ns_w packed: float4 of 4 consecutive rows at fixed col: slot (r>>2)*128+col
__device__ ulonglong2 g_nswp[8192];      // 128 KB

struct __align__(16) SimSmem {
  float nmw[HM*HH];          // nm_w packed like g_nswp (128 KB)
  float x[BMAX][HM];         // batch inputs [feats,msg]
  float b[BMAX][HM];         // [ns, msg]
  float part[BMAX*4*HH];     // GEMM partials
  float actw[HM];
  float nsb[HH], nmb[HH], g[HH];
  float tact[NN];
  float na[BMAX];
  int scanNd[SCANW], scanMid[SCANW];
  int bn[BMAX], bmid[BMAX];
  int head, tail, pops, ev, bcnt, done;
  float actb;
};

__device__ __forceinline__ unsigned long long fma2(unsigned long long a,
                                                   unsigned long long b,
                                                   unsigned long long c) {
  unsigned long long d;
  asm("fma.rn.f32x2 %0, %1, %2, %3;" : "=l"(d) : "l"(a), "l"(b), "l"(c));
  return d;
}
__device__ __forceinline__ float unpack_add(unsigned long long a) {
  float lo, hi;
  asm("mov.b64 {%0,%1}, %2;" : "=f"(lo), "=f"(hi) : "l"(a));
  return lo + hi;
}

__global__ void enc_kernel(const float* __restrict__ xa,
                           const float* __restrict__ enc_w,
                           const float* __restrict__ enc_b) {
  int n = blockIdx.x, h = threadIdx.x;
  float a = enc_b[h];
  #pragma unroll
  for (int k = 0; k < 32; k++) a = fmaf(xa[n*32 + k], enc_w[k*HH + h], a);
  g_feats[n*HH + h] = a;
}

__global__ void pack_kernel(const float* __restrict__ ns_w) {
  int r = blockIdx.x, c = threadIdx.x;
  ((float*)g_nswp)[(((r >> 2)*HH + c) << 2) + (r & 3)] = ns_w[r*HH + c];
}

// j-blocked GEMM with weights in registers (ns path)
template<int B>
__device__ __forceinline__ void gemm_reg(const ulonglong2* __restrict__ wns,
                                         SimSmem* s, int grp, int col) {
  unsigned long long acc[B];
  #pragma unroll
  for (int j = 0; j < B; j++) acc[j] = 0ULL;
  #pragma unroll
  for (int jj = 0; jj < 16; jj++) {
    ulonglong2 w = wns[jj];
    #pragma unroll
    for (int j = 0; j < B; j++) {
      ulonglong2 v = *(const ulonglong2*)(&s->x[j][grp*64 + jj*4]);
      acc[j] = fma2(w.x, v.x, acc[j]);
      acc[j] = fma2(w.y, v.y, acc[j]);
    }
  }
  #pragma unroll
  for (int j = 0; j < B; j++)
    s->part[(j*4 + grp)*HH + col] = unpack_add(acc[j]);
}

// j-blocked GEMM streaming weights from smem (nm path)
template<int B>
__device__ __forceinline__ void gemm_smem(SimSmem* s, int grp, int col) {
  unsigned long long acc[B];
  #pragma unroll
  for (int j = 0; j < B; j++) acc[j] = 0ULL;
  #pragma unroll
  for (int jj = 0; jj < 16; jj++) {
    ulonglong2 w = *(const ulonglong2*)(&s->nmw[((grp*16 + jj)*HH + col)*4]);
    #pragma unroll
    for (int j = 0; j < B; j++) {
      ulonglong2 v = *(const ulonglong2*)(&s->b[j][grp*64 + jj*4]);
      acc[j] = fma2(w.x, v.x, acc[j]);
      acc[j] = fma2(w.y, v.y, acc[j]);
    }
  }
  #pragma unroll
  for (int j = 0; j < B; j++)
    s->part[(j*4 + grp)*HH + col] = unpack_add(acc[j]);
}

__global__ __launch_bounds__(512, 1) void sim_kernel(
    const float* __restrict__ fm,   const int* __restrict__ nb,
    const int*   __restrict__ nsp,
    const float* __restrict__ nm_w,
    const float* __restrict__ ns_b, const float* __restrict__ nm_b,
    const float* __restrict__ act_w, const float* __restrict__ act_b,
    const float* __restrict__ dec_w, const float* __restrict__ dec_b,
    float* __restrict__ out)
{
  extern __shared__ char raw[];
  SimSmem* s = (SimSmem*)raw;
  const int tid = threadIdx.x;
  const int col = tid & 127;
  const int grp = tid >> 7;          // rows grp*64 .. grp*64+63
  const int wid = tid >> 5;
  const int lid = tid & 31;
  const float THRESH = 1.0f - 1e-7f;

  // ns_w: persistent register residency (64 floats/thread)
  ulonglong2 wns[16];
  #pragma unroll
  for (int jj = 0; jj < 16; jj++) wns[jj] = g_nswp[(grp*16 + jj)*HH + col];

  // nm_w: packed into smem once
  for (int i = tid; i < HM*HH; i += 512) {
    int r = i / HH, c = i % HH;
    s->nmw[(((r >> 2)*HH + c) << 2) + (r & 3)] = nm_w[i];
  }
  for (int i = tid; i < HM; i += 512) s->actw[i] = act_w[i];
  for (int i = tid; i < HH; i += 512) { s->nsb[i] = ns_b[i]; s->nmb[i] = nm_b[i]; s->g[i] = 0.f; }
  for (int i = tid; i < NN; i += 512) s->tact[i] = 0.f;
  for (int i = tid; i < BMAX*HM; i += 512) { ((float*)s->x)[i] = 0.f; ((float*)s->b)[i] = 0.f; }
  if (tid == 0) {
    int nst = nsp ? nsp[0] : 64;
    s->head = 0; s->tail = nst; s->pops = 0; s->ev = 0; s->done = 0;
    s->actb = act_b[0];
  }
  __syncthreads();
  int nstart = s->tail;
  for (int i = tid; i < nstart; i += 512) { g_qn[i] = i; g_qmid[i] = -1; }
  __syncthreads();

  while (true) {
    // ---- SELECT (warp 0 only): scan 64 entries, liveness + dup masks ----
    if (tid < 32) {
      int head = s->head, tail = s->tail, pops = s->pops;
      int L = min(SCANW, min(tail - head, MAXSTEPS - pops));
      int n0 = -1, n1 = -1;
      bool l0 = false, l1 = false;
      if (tid < L) {
        n0 = g_qn[head + tid];
        s->scanNd[tid] = n0; s->scanMid[tid] = g_qmid[head + tid];
        l0 = (s->tact[n0] <= THRESH);
      }
      if (tid + 32 < L) {
        n1 = g_qn[head + tid + 32];
        s->scanNd[tid + 32] = n1; s->scanMid[tid + 32] = g_qmid[head + tid + 32];
        l1 = (s->tact[n1] <= THRESH);
      }
      unsigned m0 = __ballot_sync(0xffffffffu, l0);
      unsigned m1 = __ballot_sync(0xffffffffu, l1);
      unsigned long long lm = (unsigned long long)m0 |
                              ((unsigned long long)m1 << 32);
      __syncwarp();
      // duplicate detection: entry k is dup if some live j<k has same node
      bool d0 = false, d1 = false;
      if (l0) {
        for (int j = 0; j < tid; j++)
          if (((lm >> j) & 1ULL) && s->scanNd[j] == n0) d0 = true;
      }
      if (l1) {
        int k1 = tid + 32;
        for (int j = 0; j < k1; j++)
          if (((lm >> j) & 1ULL) && s->scanNd[j] == n1) d1 = true;
      }
      unsigned dm0 = __ballot_sync(0xffffffffu, d0);
      unsigned dm1 = __ballot_sync(0xffffffffu, d1);
      if (lid == 0) {
        if (L <= 0) { s->done = 1; s->bcnt = 0; }
        else {
          unsigned long long dm = (unsigned long long)dm0 |
                                  ((unsigned long long)dm1 << 32);
          int dfirst = dm ? (__ffsll((long long)dm) - 1) : 64;
          int lim = min(dfirst, L);
          unsigned long long lmv =
              lm & ((lim >= 64) ? ~0ULL : ((1ULL << lim) - 1ULL));
          int nlive = __popcll(lmv);
          int bc = min(nlive, BMAX);
          int last = -1;
          unsigned long long t = lmv;
          for (int i = 0; i < bc; i++) {
            int idx = __ffsll((long long)t) - 1;
            s->bn[i] = s->scanNd[idx]; s->bmid[i] = s->scanMid[idx];
            last = idx; t &= t - 1;
          }
          int kf = (nlive >= BMAX) ? (last + 1) : lim;
          s->head = head + kf; s->pops = pops + kf; s->bcnt = bc;
        }
      }
    }
    __syncthreads();
    if (s->done) break;
    const int bcnt = s->bcnt;
    if (bcnt == 0) continue;

    // ---- C: gather batch inputs ----
    for (int i = tid; i < bcnt*HM; i += 512) {
      int j = i >> 8, k = i & 255;
      int nd = s->bn[j];
      float v;
      if (k < HH) v = g_feats[nd*HH + k];
      else {
        int md = s->bmid[j];
        v = (md < 0) ? fm[nd*MM + (k - HH)] : g_qmsg[md*MM + (k - HH)];
        s->b[j][k] = v;                   // msg half of [ns,msg]
      }
      s->x[j][k] = v;
    }
    __syncthreads();

    // ---- D: ACT (warps 0..bcnt-1) + ns GEMM (register weights) ----
    if (wid < bcnt) {
      float ap = 0.f;
      #pragma unroll
      for (int t = 0; t < 8; t++)
        ap = fmaf(s->x[wid][lid*8 + t], s->actw[lid*8 + t], ap);
      #pragma unroll
      for (int o = 16; o > 0; o >>= 1) ap += __shfl_down_sync(0xffffffffu, ap, o);
      if (lid == 0) {
        float z = ap + s->actb;
        float cand = 1.0f / (1.0f + expf(-z));
        int nd = s->bn[wid];
        float ta = s->tact[nd];
        float na = (ta + cand > 1.0f) ? (1.0f - ta) : cand;
        s->tact[nd] = ta + na;
        s->na[wid] = na;
      }
    }
    if (bcnt > 4) gemm_reg<8>(wns, s, grp, col);
    else         gemm_reg<4>(wns, s, grp, col);
    __syncthreads();

    // ---- E: finalize ns (relu, feats, s_b) ----
    for (int i = tid; i < bcnt*HH; i += 512) {
      int j = i >> 7, k = i & 127;
      float v = s->part[(j*4 + 0)*HH + k] + s->part[(j*4 + 1)*HH + k]
              + s->part[(j*4 + 2)*HH + k] + s->part[(j*4 + 3)*HH + k] + s->nsb[k];
      v = fmaxf(v, 0.f);
      s->b[j][k] = v;
      g_feats[s->bn[j]*HH + k] = v;
    }
    __syncthreads();

    // ---- F: g-accumulate + nm GEMM (smem-streamed weights) ----
    if (tid < HH) {
      float gv = s->g[tid];
      for (int j = 0; j < bcnt; j++) gv = fmaf(s->b[j][tid], s->na[j], gv);
      s->g[tid] = gv;
    }
    if (bcnt > 4) gemm_smem<8>(s, grp, col);
    else         gemm_smem<4>(s, grp, col);
    __syncthreads();

    // ---- G: finalize nm -> event store + enqueue ----
    {
      int ev = s->ev, tail = s->tail;
      for (int i = tid; i < bcnt*HH; i += 512) {
        int j = i >> 7, k = i & 127;
        float v = s->part[(j*4 + 0)*HH + k] + s->part[(j*4 + 1)*HH + k]
                + s->part[(j*4 + 2)*HH + k] + s->part[(j*4 + 3)*HH + k] + s->nmb[k];
        g_qmsg[(ev + j)*MM + k] = v;
      }
      if (tid < bcnt*DEG) {
        int j = tid >> 4, d = tid & 15;
        g_qn  [tail + j*DEG + d] = nb[s->bn[j]*DEG + d];
        g_qmid[tail + j*DEG + d] = ev + j;
      }
      if (tid == 0) { s->ev = ev + bcnt; s->tail = tail + bcnt*DEG; }
    }
    __syncthreads();
  }

  // ---- readout: logits = g @ dec_w + dec_b; log_softmax ----
  __syncthreads();
  if (tid < 20) {
    int p = tid / 10, o = tid % 10;
    float a = dec_b[p*10 + o];
    for (int h = 0; h < HH; h++) a = fmaf(s->g[h], dec_w[(p*HH + h)*10 + o], a);
    s->part[tid] = a;
  }
  __syncthreads();
  if (tid < 2) {
    float mx = -1e30f;
    for (int o = 0; o < 10; o++) mx = fmaxf(mx, s->part[tid*10 + o]);
    float sum = 0.f;
    for (int o = 0; o < 10; o++) sum += expf(s->part[tid*10 + o] - mx);
    float lse = mx + logf(sum);
    for (int o = 0; o < 10; o++) out[tid*10 + o] = s->part[tid*10 + o] - lse;
  }
}

extern "C" void kernel_launch(void* const* d_in, const int* in_sizes, int n_in,
                              void* d_out, int out_size) {
  (void)out_size;
  const float* xa = (const float*)d_in[0];
  const float* fm = (const float*)d_in[1];
  const int*   nb = (const int*)d_in[2];
  const int*   nsp = nullptr;
  int b = 3;
  if (n_in >= 14 && in_sizes[3] == 1) { nsp = (const int*)d_in[3]; b = 4; }
  const float* enc_w = (const float*)d_in[b + 0];
  const float* enc_b = (const float*)d_in[b + 1];
  const float* ns_w  = (const float*)d_in[b + 2];
  const float* ns_b  = (const float*)d_in[b + 3];
  const float* nm_w  = (const float*)d_in[b + 4];
  const float* nm_b  = (const float*)d_in[b + 5];
  const float* act_w = (const float*)d_in[b + 6];
  const float* act_b = (const float*)d_in[b + 7];
  const float* dec_w = (const float*)d_in[b + 8];
  const float* dec_b = (const float*)d_in[b + 9];

  enc_kernel<<<NN, HH>>>(xa, enc_w, enc_b);
  pack_kernel<<<HM, HH>>>(ns_w);

  cudaFuncSetAttribute(sim_kernel, cudaFuncAttributeMaxDynamicSharedMemorySize,
                       (int)sizeof(SimSmem));
  sim_kernel<<<1, 512, sizeof(SimSmem)>>>(fm, nb, nsp, nm_w, ns_b, nm_b,
                                          act_w, act_b, dec_w, dec_b,
                                          (float*)d_out);
}

// round 6
// speedup vs baseline: 2.0729x; 1.1209x over previous
#include <cuda_runtime.h>
#include <math.h>

#define NN  1000
#define HH  128
#define MM  128
#define HM  256
#define DEG 16
#define MAXSTEPS 10000
#define CAPQ (NN + MAXSTEPS*DEG + 128)
#define BMAX 16
#define SCANW 128

// Persistent device scratch (no allocation allowed)
__device__ float g_feats[NN*HH];
__device__ int   g_qn  [CAPQ];
__device__ int   g_qmid[CAPQ];           // -1 => first_message[node]
__device__ float g_qmsg[MAXSTEPS*MM];
// ns_w packed: float4 of 4 consecutive rows at fixed col: slot (r>>2)*128+col
__device__ ulonglong2 g_nswp[8192];      // 128 KB

struct __align__(16) SimSmem {
  float nmw[HM*HH];          // nm_w packed like g_nswp (128 KB)
  float x[BMAX][HM];         // batch inputs [feats,msg]
  float b[BMAX][HM];         // [ns, msg]
  float part[BMAX*4*HH];     // GEMM partials (32 KB)
  float actw[HM];
  float nsb[HH], nmb[HH], g[HH];
  float tact[NN];
  float na[BMAX];
  int   mark[NN];            // select: first-occurrence slot per node
  int scanNd[SCANW], scanMid[SCANW];
  int bn[BMAX], bmid[BMAX];
  int head, tail, pops, ev, bcnt, done, kf16;
  float actb;
};

__device__ __forceinline__ unsigned long long fma2(unsigned long long a,
                                                   unsigned long long b,
                                                   unsigned long long c) {
  unsigned long long d;
  asm("fma.rn.f32x2 %0, %1, %2, %3;" : "=l"(d) : "l"(a), "l"(b), "l"(c));
  return d;
}
__device__ __forceinline__ float unpack_add(unsigned long long a) {
  float lo, hi;
  asm("mov.b64 {%0,%1}, %2;" : "=f"(lo), "=f"(hi) : "l"(a));
  return lo + hi;
}

__global__ void enc_kernel(const float* __restrict__ xa,
                           const float* __restrict__ enc_w,
                           const float* __restrict__ enc_b) {
  int n = blockIdx.x, h = threadIdx.x;
  float a = enc_b[h];
  #pragma unroll
  for (int k = 0; k < 32; k++) a = fmaf(xa[n*32 + k], enc_w[k*HH + h], a);
  g_feats[n*HH + h] = a;
}

__global__ void pack_kernel(const float* __restrict__ ns_w) {
  int r = blockIdx.x, c = threadIdx.x;
  ((float*)g_nswp)[(((r >> 2)*HH + c) << 2) + (r & 3)] = ns_w[r*HH + c];
}

// j-blocked GEMM with weights in registers (ns path), batch offset OFF
template<int B>
__device__ __forceinline__ void gemm_reg(const ulonglong2* __restrict__ wns,
                                         SimSmem* s, int grp, int col, int off) {
  unsigned long long acc[B];
  #pragma unroll
  for (int j = 0; j < B; j++) acc[j] = 0ULL;
  #pragma unroll
  for (int jj = 0; jj < 16; jj++) {
    ulonglong2 w = wns[jj];
    #pragma unroll
    for (int j = 0; j < B; j++) {
      ulonglong2 v = *(const ulonglong2*)(&s->x[off + j][grp*64 + jj*4]);
      acc[j] = fma2(w.x, v.x, acc[j]);
      acc[j] = fma2(w.y, v.y, acc[j]);
    }
  }
  #pragma unroll
  for (int j = 0; j < B; j++)
    s->part[((off + j)*4 + grp)*HH + col] = unpack_add(acc[j]);
}

// j-blocked GEMM streaming weights from smem (nm path)
template<int B>
__device__ __forceinline__ void gemm_smem(SimSmem* s, int grp, int col, int off) {
  unsigned long long acc[B];
  #pragma unroll
  for (int j = 0; j < B; j++) acc[j] = 0ULL;
  #pragma unroll
  for (int jj = 0; jj < 16; jj++) {
    ulonglong2 w = *(const ulonglong2*)(&s->nmw[((grp*16 + jj)*HH + col)*4]);
    #pragma unroll
    for (int j = 0; j < B; j++) {
      ulonglong2 v = *(const ulonglong2*)(&s->b[off + j][grp*64 + jj*4]);
      acc[j] = fma2(w.x, v.x, acc[j]);
      acc[j] = fma2(w.y, v.y, acc[j]);
    }
  }
  #pragma unroll
  for (int j = 0; j < B; j++)
    s->part[((off + j)*4 + grp)*HH + col] = unpack_add(acc[j]);
}

__global__ __launch_bounds__(512, 1) void sim_kernel(
    const float* __restrict__ fm,   const int* __restrict__ nb,
    const int*   __restrict__ nsp,
    const float* __restrict__ nm_w,
    const float* __restrict__ ns_b, const float* __restrict__ nm_b,
    const float* __restrict__ act_w, const float* __restrict__ act_b,
    const float* __restrict__ dec_w, const float* __restrict__ dec_b,
    float* __restrict__ out)
{
  extern __shared__ char raw[];
  SimSmem* s = (SimSmem*)raw;
  const int tid = threadIdx.x;
  const int col = tid & 127;
  const int grp = tid >> 7;          // rows grp*64 .. grp*64+63
  const int wid = tid >> 5;
  const int lid = tid & 31;
  const float THRESH = 1.0f - 1e-7f;

  // ns_w: persistent register residency (64 floats/thread)
  ulonglong2 wns[16];
  #pragma unroll
  for (int jj = 0; jj < 16; jj++) wns[jj] = g_nswp[(grp*16 + jj)*HH + col];

  // nm_w: packed into smem once
  for (int i = tid; i < HM*HH; i += 512) {
    int r = i / HH, c = i % HH;
    s->nmw[(((r >> 2)*HH + c) << 2) + (r & 3)] = nm_w[i];
  }
  for (int i = tid; i < HM; i += 512) s->actw[i] = act_w[i];
  for (int i = tid; i < HH; i += 512) { s->nsb[i] = ns_b[i]; s->nmb[i] = nm_b[i]; s->g[i] = 0.f; }
  for (int i = tid; i < NN; i += 512) { s->tact[i] = 0.f; s->mark[i] = 0x7fffffff; }
  for (int i = tid; i < BMAX*HM; i += 512) { ((float*)s->x)[i] = 0.f; ((float*)s->b)[i] = 0.f; }
  if (tid == 0) {
    int nst = nsp ? nsp[0] : 64;
    s->head = 0; s->tail = nst; s->pops = 0; s->ev = 0; s->done = 0;
    s->actb = act_b[0];
  }
  __syncthreads();
  int nstart = s->tail;
  for (int i = tid; i < nstart; i += 512) { g_qn[i] = i; g_qmid[i] = -1; }
  __syncthreads();

  while (true) {
    // ---- SELECT (warp 0): scan up to 128 entries, fully parallel ----
    if (tid < 32) {
      int head = s->head, tail = s->tail, pops = s->pops;
      int L = min(SCANW, min(tail - head, MAXSTEPS - pops));
      int nd[4], md[4];
      bool lv[4];
      unsigned m[4];
      #pragma unroll
      for (int t = 0; t < 4; t++) {
        int k = lid + 32*t;
        lv[t] = false; nd[t] = -1;
        if (k < L) {
          nd[t] = g_qn[head + k];
          md[t] = g_qmid[head + k];
          s->scanNd[k] = nd[t]; s->scanMid[k] = md[t];
          lv[t] = (s->tact[nd[t]] <= THRESH);
        }
        m[t] = __ballot_sync(0xffffffffu, lv[t]);
      }
      unsigned long long lmlo = (unsigned long long)m[0] | ((unsigned long long)m[1] << 32);
      unsigned long long lmhi = (unsigned long long)m[2] | ((unsigned long long)m[3] << 32);
      // first-occurrence marking
      #pragma unroll
      for (int t = 0; t < 4; t++)
        if (lv[t]) atomicMin(&s->mark[nd[t]], lid + 32*t);
      __syncwarp();
      unsigned d[4];
      #pragma unroll
      for (int t = 0; t < 4; t++) {
        bool dup = lv[t] && (s->mark[nd[t]] != lid + 32*t);
        d[t] = __ballot_sync(0xffffffffu, dup);
      }
      __syncwarp();
      #pragma unroll
      for (int t = 0; t < 4; t++)
        if (lv[t]) s->mark[nd[t]] = 0x7fffffff;   // reset touched
      unsigned long long dmlo = (unsigned long long)d[0] | ((unsigned long long)d[1] << 32);
      unsigned long long dmhi = (unsigned long long)d[2] | ((unsigned long long)d[3] << 32);
      // uniform: first dup position, limit, masked live mask
      int dfirst = dmlo ? (__ffsll((long long)dmlo) - 1)
                 : (dmhi ? 64 + (__ffsll((long long)dmhi) - 1) : 128);
      int lim = min(dfirst, L);
      unsigned long long vlo = lmlo, vhi = lmhi;
      if (lim < 64)       { vlo &= (1ULL << lim) - 1ULL; vhi = 0ULL; }
      else if (lim < 128) { vhi &= (1ULL << (lim - 64)) - 1ULL; }
      int nlive = __popcll(vlo) + __popcll(vhi);
      int bc = min(nlive, BMAX);
      // rank-based parallel batch extraction
      #pragma unroll
      for (int t = 0; t < 4; t++) {
        int k = lid + 32*t;
        bool sel = lv[t] && (k < lim);
        if (sel) {
          int rank;
          if (k < 64) rank = __popcll(vlo & ((1ULL << k) - 1ULL));
          else        rank = __popcll(vlo) + __popcll(vhi & ((k == 64) ? 0ULL : ((1ULL << (k - 64)) - 1ULL)));
          if (rank < BMAX) { s->bn[rank] = nd[t]; s->bmid[rank] = md[t]; }
          if (rank == BMAX - 1) s->kf16 = k + 1;
        }
      }
      __syncwarp();
      if (lid == 0) {
        if (L <= 0) { s->done = 1; s->bcnt = 0; }
        else {
          int kf = (nlive >= BMAX) ? s->kf16 : lim;
          s->head = head + kf; s->pops = pops + kf; s->bcnt = bc;
        }
      }
    }
    __syncthreads();
    if (s->done) break;
    const int bcnt = s->bcnt;
    if (bcnt == 0) continue;

    // ---- C: gather batch inputs ----
    for (int i = tid; i < bcnt*HM; i += 512) {
      int j = i >> 8, k = i & 255;
      int ndg = s->bn[j];
      float v;
      if (k < HH) v = g_feats[ndg*HH + k];
      else {
        int mdg = s->bmid[j];
        v = (mdg < 0) ? fm[ndg*MM + (k - HH)] : g_qmsg[mdg*MM + (k - HH)];
        s->b[j][k] = v;                   // msg half of [ns,msg]
      }
      s->x[j][k] = v;
    }
    __syncthreads();

    // ---- D: ACT (one warp per batch entry) + ns GEMM (register weights) ----
    if (wid < bcnt) {
      float ap = 0.f;
      #pragma unroll
      for (int t = 0; t < 8; t++)
        ap = fmaf(s->x[wid][lid*8 + t], s->actw[lid*8 + t], ap);
      #pragma unroll
      for (int o = 16; o > 0; o >>= 1) ap += __shfl_down_sync(0xffffffffu, ap, o);
      if (lid == 0) {
        float z = ap + s->actb;
        float cand = 1.0f / (1.0f + expf(-z));
        int ndl = s->bn[wid];
        float ta = s->tact[ndl];
        float na = (ta + cand > 1.0f) ? (1.0f - ta) : cand;
        s->tact[ndl] = ta + na;
        s->na[wid] = na;
      }
    }
    if      (bcnt <= 4)  gemm_reg<4>(wns, s, grp, col, 0);
    else if (bcnt <= 8)  gemm_reg<8>(wns, s, grp, col, 0);
    else if (bcnt <= 12) { gemm_reg<8>(wns, s, grp, col, 0); gemm_reg<4>(wns, s, grp, col, 8); }
    else                 { gemm_reg<8>(wns, s, grp, col, 0); gemm_reg<8>(wns, s, grp, col, 8); }
    __syncthreads();

    // ---- E: finalize ns (relu, feats, s_b) ----
    for (int i = tid; i < bcnt*HH; i += 512) {
      int j = i >> 7, k = i & 127;
      float v = s->part[(j*4 + 0)*HH + k] + s->part[(j*4 + 1)*HH + k]
              + s->part[(j*4 + 2)*HH + k] + s->part[(j*4 + 3)*HH + k] + s->nsb[k];
      v = fmaxf(v, 0.f);
      s->b[j][k] = v;
      g_feats[s->bn[j]*HH + k] = v;
    }
    __syncthreads();

    // ---- F: g-accumulate (queue order preserved) + nm GEMM (smem weights) ----
    if (tid < HH) {
      float gv = s->g[tid];
      for (int j = 0; j < bcnt; j++) gv = fmaf(s->b[j][tid], s->na[j], gv);
      s->g[tid] = gv;
    }
    if      (bcnt <= 4)  gemm_smem<4>(s, grp, col, 0);
    else if (bcnt <= 8)  gemm_smem<8>(s, grp, col, 0);
    else if (bcnt <= 12) { gemm_smem<8>(s, grp, col, 0); gemm_smem<4>(s, grp, col, 8); }
    else                 { gemm_smem<8>(s, grp, col, 0); gemm_smem<8>(s, grp, col, 8); }
    __syncthreads();

    // ---- G: finalize nm -> event store + enqueue ----
    {
      int ev = s->ev, tail = s->tail;
      for (int i = tid; i < bcnt*HH; i += 512) {
        int j = i >> 7, k = i & 127;
        float v = s->part[(j*4 + 0)*HH + k] + s->part[(j*4 + 1)*HH + k]
                + s->part[(j*4 + 2)*HH + k] + s->part[(j*4 + 3)*HH + k] + s->nmb[k];
        g_qmsg[(ev + j)*MM + k] = v;
      }
      if (tid < bcnt*DEG) {
        int j = tid >> 4, dd = tid & 15;
        g_qn  [tail + j*DEG + dd] = nb[s->bn[j]*DEG + dd];
        g_qmid[tail + j*DEG + dd] = ev + j;
      }
      if (tid == 0) { s->ev = ev + bcnt; s->tail = tail + bcnt*DEG; }
    }
    __syncthreads();
  }

  // ---- readout: logits = g @ dec_w + dec_b; log_softmax ----
  __syncthreads();
  if (tid < 20) {
    int p = tid / 10, o = tid % 10;
    float a = dec_b[p*10 + o];
    for (int h = 0; h < HH; h++) a = fmaf(s->g[h], dec_w[(p*HH + h)*10 + o], a);
    s->part[tid] = a;
  }
  __syncthreads();
  if (tid < 2) {
    float mx = -1e30f;
    for (int o = 0; o < 10; o++) mx = fmaxf(mx, s->part[tid*10 + o]);
    float sum = 0.f;
    for (int o = 0; o < 10; o++) sum += expf(s->part[tid*10 + o] - mx);
    float lse = mx + logf(sum);
    for (int o = 0; o < 10; o++) out[tid*10 + o] = s->part[tid*10 + o] - lse;
  }
}

extern "C" void kernel_launch(void* const* d_in, const int* in_sizes, int n_in,
                              void* d_out, int out_size) {
  (void)out_size;
  const float* xa = (const float*)d_in[0];
  const float* fm = (const float*)d_in[1];
  const int*   nb = (const int*)d_in[2];
  const int*   nsp = nullptr;
  int b = 3;
  if (n_in >= 14 && in_sizes[3] == 1) { nsp = (const int*)d_in[3]; b = 4; }
  const float* enc_w = (const float*)d_in[b + 0];
  const float* enc_b = (const float*)d_in[b + 1];
  const float* ns_w  = (const float*)d_in[b + 2];
  const float* ns_b  = (const float*)d_in[b + 3];
  const float* nm_w  = (const float*)d_in[b + 4];
  const float* nm_b  = (const float*)d_in[b + 5];
  const float* act_w = (const float*)d_in[b + 6];
  const float* act_b = (const float*)d_in[b + 7];
  const float* dec_w = (const float*)d_in[b + 8];
  const float* dec_b = (const float*)d_in[b + 9];

  enc_kernel<<<NN, HH>>>(xa, enc_w, enc_b);
  pack_kernel<<<HM, HH>>>(ns_w);

  cudaFuncSetAttribute(sim_kernel, cudaFuncAttributeMaxDynamicSharedMemorySize,
                       (int)sizeof(SimSmem));
  sim_kernel<<<1, 512, sizeof(SimSmem)>>>(fm, nb, nsp, nm_w, ns_b, nm_b,
                                          act_w, act_b, dec_w, dec_b,
                                          (float*)d_out);
}

// round 8
// speedup vs baseline: 2.2754x; 1.0977x over previous
#include <cuda_runtime.h>
#include <math.h>

#define NN  1000
#define HH  128
#define MM  128
#define HM  256
#define DEG 16
#define MAXSTEPS 10000
#define CAPQ (NN + MAXSTEPS*DEG + 128)
#define BMAX 16
#define SCANW 128
#define NG   8      // row groups
#define RPG  32     // rows per group
#define NT   1024

// Persistent device scratch (no allocation allowed)
__device__ float g_feats[NN*HH];
__device__ int   g_qn  [CAPQ];
__device__ int   g_qmid[CAPQ];           // -1 => first_message[node]
__device__ float g_qmsg[MAXSTEPS*MM];
// ns_w packed: float4 of 4 consecutive rows at fixed col: slot (r>>2)*128+col
__device__ ulonglong2 g_nswp[8192];      // 128 KB

struct __align__(16) SimSmem {
  float nmw[HM*HH];          // nm_w packed like g_nswp (128 KB)
  float x[BMAX][HM];         // batch inputs [feats,msg]
  float b[BMAX][HM];         // [ns, msg]
  float part[8*NG*HH];       // partials: 8 j-entries x 8 groups x 128 (32 KB)
  float actw[HM];
  float nsb[HH], nmb[HH], g[HH];
  float tact[NN];
  float na[BMAX];
  int   mark[NN];
  int scanNd[SCANW], scanMid[SCANW];
  int bn[BMAX], bmid[BMAX];
  int head, tail, pops, ev, bcnt, done, kf16, evb, tailb;
  float actb;
};

__device__ __forceinline__ unsigned long long fma2(unsigned long long a,
                                                   unsigned long long b,
                                                   unsigned long long c) {
  unsigned long long d;
  asm("fma.rn.f32x2 %0, %1, %2, %3;" : "=l"(d) : "l"(a), "l"(b), "l"(c));
  return d;
}
__device__ __forceinline__ float unpack_add(unsigned long long a) {
  float lo, hi;
  asm("mov.b64 {%0,%1}, %2;" : "=f"(lo), "=f"(hi) : "l"(a));
  return lo + hi;
}

__global__ void enc_kernel(const float* __restrict__ xa,
                           const float* __restrict__ enc_w,
                           const float* __restrict__ enc_b) {
  int n = blockIdx.x, h = threadIdx.x;
  float a = enc_b[h];
  #pragma unroll
  for (int k = 0; k < 32; k++) a = fmaf(xa[n*32 + k], enc_w[k*HH + h], a);
  g_feats[n*HH + h] = a;
}

__global__ void pack_kernel(const float* __restrict__ ns_w) {
  int r = blockIdx.x, c = threadIdx.x;
  ((float*)g_nswp)[(((r >> 2)*HH + c) << 2) + (r & 3)] = ns_w[r*HH + c];
}

// ns GEMM: weights in regs (8 x ulonglong2 = rows grp*32..+31), j-half at `off`
template<int B>
__device__ __forceinline__ void gemm_reg(const ulonglong2* __restrict__ wns,
                                         SimSmem* s, int grp, int col, int off) {
  unsigned long long acc[B];
  #pragma unroll
  for (int j = 0; j < B; j++) acc[j] = 0ULL;
  #pragma unroll
  for (int jj = 0; jj < 8; jj++) {
    ulonglong2 w = wns[jj];
    #pragma unroll
    for (int j = 0; j < B; j++) {
      ulonglong2 v = *(const ulonglong2*)(&s->x[off + j][grp*RPG + jj*4]);
      acc[j] = fma2(w.x, v.x, acc[j]);
      acc[j] = fma2(w.y, v.y, acc[j]);
    }
  }
  #pragma unroll
  for (int j = 0; j < B; j++)
    s->part[(j*NG + grp)*HH + col] = unpack_add(acc[j]);
}

// nm GEMM: weights streamed from smem
template<int B>
__device__ __forceinline__ void gemm_smem(SimSmem* s, int grp, int col, int off) {
  unsigned long long acc[B];
  #pragma unroll
  for (int j = 0; j < B; j++) acc[j] = 0ULL;
  #pragma unroll
  for (int jj = 0; jj < 8; jj++) {
    ulonglong2 w = *(const ulonglong2*)(&s->nmw[((grp*8 + jj)*HH + col)*4]);
    #pragma unroll
    for (int j = 0; j < B; j++) {
      ulonglong2 v = *(const ulonglong2*)(&s->b[off + j][grp*RPG + jj*4]);
      acc[j] = fma2(w.x, v.x, acc[j]);
      acc[j] = fma2(w.y, v.y, acc[j]);
    }
  }
  #pragma unroll
  for (int j = 0; j < B; j++)
    s->part[(j*NG + grp)*HH + col] = unpack_add(acc[j]);
}

__device__ __forceinline__ void fin_ns(SimSmem* s, int off, int cnt, int tid) {
  for (int i = tid; i < cnt*HH; i += NT) {
    int j = i >> 7, k = i & 127;
    float v = s->nsb[k];
    #pragma unroll
    for (int gg = 0; gg < NG; gg++) v += s->part[(j*NG + gg)*HH + k];
    v = fmaxf(v, 0.f);
    s->b[off + j][k] = v;
    g_feats[s->bn[off + j]*HH + k] = v;
  }
}

__device__ __forceinline__ void fin_nm(SimSmem* s, int off, int cnt, int tid, int evb) {
  for (int i = tid; i < cnt*HH; i += NT) {
    int j = i >> 7, k = i & 127;
    float v = s->nmb[k];
    #pragma unroll
    for (int gg = 0; gg < NG; gg++) v += s->part[(j*NG + gg)*HH + k];
    g_qmsg[(evb + off + j)*MM + k] = v;
  }
}

__global__ __launch_bounds__(NT, 1) void sim_kernel(
    const float* __restrict__ fm,   const int* __restrict__ nb,
    const int*   __restrict__ nsp,
    const float* __restrict__ nm_w,
    const float* __restrict__ ns_b, const float* __restrict__ nm_b,
    const float* __restrict__ act_w, const float* __restrict__ act_b,
    const float* __restrict__ dec_w, const float* __restrict__ dec_b,
    float* __restrict__ out)
{
  extern __shared__ char raw[];
  SimSmem* s = (SimSmem*)raw;
  const int tid = threadIdx.x;
  const int col = tid & 127;
  const int grp = tid >> 7;          // 0..7 -> rows grp*32 .. grp*32+31
  const int wid = tid >> 5;
  const int lid = tid & 31;
  const float THRESH = 1.0f - 1e-7f;

  // ns_w: persistent register residency (32 floats/thread)
  ulonglong2 wns[8];
  #pragma unroll
  for (int jj = 0; jj < 8; jj++) wns[jj] = g_nswp[(grp*8 + jj)*HH + col];

  // nm_w: packed into smem once
  for (int i = tid; i < HM*HH; i += NT) {
    int r = i / HH, c = i % HH;
    s->nmw[(((r >> 2)*HH + c) << 2) + (r & 3)] = nm_w[i];
  }
  for (int i = tid; i < HM; i += NT) s->actw[i] = act_w[i];
  for (int i = tid; i < HH; i += NT) { s->nsb[i] = ns_b[i]; s->nmb[i] = nm_b[i]; s->g[i] = 0.f; }
  for (int i = tid; i < NN; i += NT) { s->tact[i] = 0.f; s->mark[i] = 0x7fffffff; }
  for (int i = tid; i < BMAX*HM; i += NT) { ((float*)s->x)[i] = 0.f; ((float*)s->b)[i] = 0.f; }
  if (tid == 0) {
    int nst = nsp ? nsp[0] : 64;
    s->head = 0; s->tail = nst; s->pops = 0; s->ev = 0; s->done = 0;
    s->actb = act_b[0];
  }
  __syncthreads();
  int nstart = s->tail;
  for (int i = tid; i < nstart; i += NT) { g_qn[i] = i; g_qmid[i] = -1; }
  __syncthreads();

  while (true) {
    // ---- SELECT (warp 0): scan up to 128 entries, fully parallel ----
    if (tid < 32) {
      int head = s->head, tail = s->tail, pops = s->pops;
      int L = min(SCANW, min(tail - head, MAXSTEPS - pops));
      int nd[4], md[4];
      bool lv[4];
      unsigned m[4];
      #pragma unroll
      for (int t = 0; t < 4; t++) {
        int k = lid + 32*t;
        lv[t] = false; nd[t] = -1;
        if (k < L) {
          nd[t] = g_qn[head + k];
          md[t] = g_qmid[head + k];
          s->scanNd[k] = nd[t]; s->scanMid[k] = md[t];
          lv[t] = (s->tact[nd[t]] <= THRESH);
        }
        m[t] = __ballot_sync(0xffffffffu, lv[t]);
      }
      unsigned long long lmlo = (unsigned long long)m[0] | ((unsigned long long)m[1] << 32);
      unsigned long long lmhi = (unsigned long long)m[2] | ((unsigned long long)m[3] << 32);
      #pragma unroll
      for (int t = 0; t < 4; t++)
        if (lv[t]) atomicMin(&s->mark[nd[t]], lid + 32*t);
      __syncwarp();
      unsigned d[4];
      #pragma unroll
      for (int t = 0; t < 4; t++) {
        bool dup = lv[t] && (s->mark[nd[t]] != lid + 32*t);
        d[t] = __ballot_sync(0xffffffffu, dup);
      }
      __syncwarp();
      #pragma unroll
      for (int t = 0; t < 4; t++)
        if (lv[t]) s->mark[nd[t]] = 0x7fffffff;   // reset touched
      unsigned long long dmlo = (unsigned long long)d[0] | ((unsigned long long)d[1] << 32);
      unsigned long long dmhi = (unsigned long long)d[2] | ((unsigned long long)d[3] << 32);
      int dfirst = dmlo ? (__ffsll((long long)dmlo) - 1)
                 : (dmhi ? 64 + (__ffsll((long long)dmhi) - 1) : 128);
      int lim = min(dfirst, L);
      unsigned long long vlo = lmlo, vhi = lmhi;
      if (lim < 64)       { vlo &= (1ULL << lim) - 1ULL; vhi = 0ULL; }
      else if (lim < 128) { vhi &= (1ULL << (lim - 64)) - 1ULL; }
      int nlive = __popcll(vlo) + __popcll(vhi);
      int bc = min(nlive, BMAX);
      #pragma unroll
      for (int t = 0; t < 4; t++) {
        int k = lid + 32*t;
        bool sel = lv[t] && (k < lim);
        if (sel) {
          int rank;
          if (k < 64) rank = __popcll(vlo & ((1ULL << k) - 1ULL));
          else        rank = __popcll(vlo) + __popcll(vhi & ((k == 64) ? 0ULL : ((1ULL << (k - 64)) - 1ULL)));
          if (rank < BMAX) { s->bn[rank] = nd[t]; s->bmid[rank] = md[t]; }
          if (rank == BMAX - 1) s->kf16 = k + 1;
        }
      }
      __syncwarp();
      if (lid == 0) {
        if (L <= 0) { s->done = 1; s->bcnt = 0; }
        else {
          int kf = (nlive >= BMAX) ? s->kf16 : lim;
          s->head = head + kf; s->pops = pops + kf; s->bcnt = bc;
          s->evb = s->ev; s->tailb = tail;
          s->ev += bc; s->tail = tail + bc*DEG;
        }
      }
    }
    __syncthreads();
    if (s->done) break;
    const int bcnt = s->bcnt;
    if (bcnt == 0) continue;
    const int c0 = min(bcnt, 8), c1 = bcnt - c0;
    const int evb = s->evb, tailb = s->tailb;

    // ---- gather batch inputs + enqueue neighbor refs ----
    for (int i = tid; i < bcnt*HM; i += NT) {
      int j = i >> 8, k = i & 255;
      int ndg = s->bn[j];
      float v;
      if (k < HH) v = g_feats[ndg*HH + k];
      else {
        int mdg = s->bmid[j];
        v = (mdg < 0) ? fm[ndg*MM + (k - HH)] : g_qmsg[mdg*MM + (k - HH)];
        s->b[j][k] = v;                   // msg half of [ns,msg]
      }
      s->x[j][k] = v;
    }
    if (tid >= NT - 256 && tid - (NT - 256) < bcnt*DEG) {
      int e = tid - (NT - 256);
      int j = e >> 4, dd = e & 15;
      g_qn  [tailb + e] = nb[s->bn[j]*DEG + dd];
      g_qmid[tailb + e] = evb + j;
    }
    __syncthreads();

    // ---- ACT (one warp per entry) + ns GEMM half0 ----
    if (wid < bcnt) {
      float ap = 0.f;
      #pragma unroll
      for (int t = 0; t < 8; t++)
        ap = fmaf(s->x[wid][lid*8 + t], s->actw[lid*8 + t], ap);
      #pragma unroll
      for (int o = 16; o > 0; o >>= 1) ap += __shfl_down_sync(0xffffffffu, ap, o);
      if (lid == 0) {
        float z = ap + s->actb;
        float cand = 1.0f / (1.0f + expf(-z));
        int ndl = s->bn[wid];
        float ta = s->tact[ndl];
        float na = (ta + cand > 1.0f) ? (1.0f - ta) : cand;
        s->tact[ndl] = ta + na;
        s->na[wid] = na;
      }
    }
    if (c0 <= 4) gemm_reg<4>(wns, s, grp, col, 0);
    else         gemm_reg<8>(wns, s, grp, col, 0);
    __syncthreads();
    fin_ns(s, 0, c0, tid);
    __syncthreads();
    if (c1 > 0) {
      if (c1 <= 4) gemm_reg<4>(wns, s, grp, col, 8);
      else         gemm_reg<8>(wns, s, grp, col, 8);
      __syncthreads();
      fin_ns(s, 8, c1, tid);
      __syncthreads();
    }

    // ---- g-accumulate (queue order) + nm GEMM half0 ----
    if (tid < HH) {
      float gv = s->g[tid];
      for (int j = 0; j < bcnt; j++) gv = fmaf(s->b[j][tid], s->na[j], gv);
      s->g[tid] = gv;
    }
    if (c0 <= 4) gemm_smem<4>(s, grp, col, 0);
    else         gemm_smem<8>(s, grp, col, 0);
    __syncthreads();
    fin_nm(s, 0, c0, tid, evb);
    __syncthreads();
    if (c1 > 0) {
      if (c1 <= 4) gemm_smem<4>(s, grp, col, 8);
      else         gemm_smem<8>(s, grp, col, 8);
      __syncthreads();
      fin_nm(s, 8, c1, tid, evb);
      __syncthreads();
    }
  }

  // ---- readout: logits = g @ dec_w + dec_b; log_softmax ----
  __syncthreads();
  if (tid < 20) {
    int p = tid / 10, o = tid % 10;
    float a = dec_b[p*10 + o];
    for (int h = 0; h < HH; h++) a = fmaf(s->g[h], dec_w[(p*HH + h)*10 + o], a);
    s->part[tid] = a;
  }
  __syncthreads();
  if (tid < 2) {
    float mx = -1e30f;
    for (int o = 0; o < 10; o++) mx = fmaxf(mx, s->part[tid*10 + o]);
    float sum = 0.f;
    for (int o = 0; o < 10; o++) sum += expf(s->part[tid*10 + o] - mx);
    float lse = mx + logf(sum);
    for (int o = 0; o < 10; o++) out[tid*10 + o] = s->part[tid*10 + o] - lse;
  }
}

extern "C" void kernel_launch(void* const* d_in, const int* in_sizes, int n_in,
                              void* d_out, int out_size) {
  (void)out_size;
  const float* xa = (const float*)d_in[0];
  const float* fm = (const float*)d_in[1];
  const int*   nb = (const int*)d_in[2];
  const int*   nsp = nullptr;
  int b = 3;
  if (n_in >= 14 && in_sizes[3] == 1) { nsp = (const int*)d_in[3]; b = 4; }
  const float* enc_w = (const float*)d_in[b + 0];
  const float* enc_b = (const float*)d_in[b + 1];
  const float* ns_w  = (const float*)d_in[b + 2];
  const float* ns_b  = (const float*)d_in[b + 3];
  const float* nm_w  = (const float*)d_in[b + 4];
  const float* nm_b  = (const float*)d_in[b + 5];
  const float* act_w = (const float*)d_in[b + 6];
  const float* act_b = (const float*)d_in[b + 7];
  const float* dec_w = (const float*)d_in[b + 8];
  const float* dec_b = (const float*)d_in[b + 9];

  enc_kernel<<<NN, HH>>>(xa, enc_w, enc_b);
  pack_kernel<<<HM, HH>>>(ns_w);

  cudaFuncSetAttribute(sim_kernel, cudaFuncAttributeMaxDynamicSharedMemorySize,
                       (int)sizeof(SimSmem));
  sim_kernel<<<1, NT, sizeof(SimSmem)>>>(fm, nb, nsp, nm_w, ns_b, nm_b,
                                         act_w, act_b, dec_w, dec_b,
                                         (float*)d_out);
}

// round 10
// speedup vs baseline: 2.9774x; 1.3085x over previous
#include <cuda_runtime.h>
#include <stdint.h>
#include <math.h>

#define NN  1000
#define HH  128
#define MM  128
#define HM  256
#define DEG 16
#define MAXSTEPS 10000
#define CAPQ (NN + MAXSTEPS*DEG + 128)
#define BMAX 16
#define SCANW 128
#define NT   1024
#define NGC  16     // row groups (16 rows each)
#define CPC  64     // cols per CTA

// Persistent device scratch (no allocation allowed)
__device__ float g_feats[NN*HH];
__device__ int   g_qn  [CAPQ];
__device__ int   g_qmid[CAPQ];           // -1 => first_message[node]
__device__ float g_qmsg[MAXSTEPS*MM];
// weights packed: float4 of 4 consecutive rows at fixed col: slot (r>>2)*128+col
__device__ float g_nswp[HM*HH];
__device__ float g_nmwp[HM*HH];

struct __align__(16) SimSmem {
  float x[BMAX][HM];         // batch inputs [feats,msg]  (16 KB)
  float b[BMAX][HM];         // [ns, msg] — full via DSMEM exchange (16 KB)
  float part[8*NGC*CPC];     // partials: 8 j x 16 grp x 64 col (32 KB)
  float actw[HM];
  float nsb[HH], nmb[HH], g[HH];
  float tact[NN];
  float na[BMAX];
  int   mark[NN];
  int scanNd[SCANW], scanMid[SCANW];
  int bn[BMAX], bmid[BMAX];
  int head, tail, pops, ev;
  int bcnt, evb, tailb, done, kf16;
  float actb;
};

__device__ __forceinline__ unsigned long long fma2(unsigned long long a,
                                                   unsigned long long b,
                                                   unsigned long long c) {
  unsigned long long d;
  asm("fma.rn.f32x2 %0, %1, %2, %3;" : "=l"(d) : "l"(a), "l"(b), "l"(c));
  return d;
}
__device__ __forceinline__ float unpack_add(unsigned long long a) {
  float lo, hi;
  asm("mov.b64 {%0,%1}, %2;" : "=f"(lo), "=f"(hi) : "l"(a));
  return lo + hi;
}
__device__ __forceinline__ uint32_t smem_u32(const void* p) {
  uint32_t a;
  asm("{ .reg .u64 t; cvta.to.shared.u64 t, %1; cvt.u32.u64 %0, t; }"
      : "=r"(a) : "l"(p));
  return a;
}
__device__ __forceinline__ void st_remote_f32(uint32_t laddr, int peer, float v) {
  uint32_t ra;
  asm("mapa.shared::cluster.u32 %0, %1, %2;" : "=r"(ra) : "r"(laddr), "r"(peer));
  asm volatile("st.shared::cluster.f32 [%0], %1;" :: "r"(ra), "f"(v) : "memory");
}
__device__ __forceinline__ void st_remote_s32(uint32_t laddr, int peer, int v) {
  uint32_t ra;
  asm("mapa.shared::cluster.u32 %0, %1, %2;" : "=r"(ra) : "r"(laddr), "r"(peer));
  asm volatile("st.shared::cluster.b32 [%0], %1;" :: "r"(ra), "r"(v) : "memory");
}
__device__ __forceinline__ uint32_t ctarank() {
  uint32_t r; asm("mov.u32 %0, %%cluster_ctarank;" : "=r"(r)); return r;
}
#define CSYNC() do { \
  asm volatile("barrier.cluster.arrive.aligned;" ::: "memory"); \
  asm volatile("barrier.cluster.wait.aligned;"   ::: "memory"); } while (0)

__global__ void enc_kernel(const float* __restrict__ xa,
                           const float* __restrict__ enc_w,
                           const float* __restrict__ enc_b) {
  int n = blockIdx.x, h = threadIdx.x;
  float a = enc_b[h];
  #pragma unroll
  for (int k = 0; k < 32; k++) a = fmaf(xa[n*32 + k], enc_w[k*HH + h], a);
  g_feats[n*HH + h] = a;
}

__global__ void pack_kernel(const float* __restrict__ ns_w,
                            const float* __restrict__ nm_w) {
  int r = blockIdx.x, c = threadIdx.x;
  int dst = (((r >> 2)*HH + c) << 2) + (r & 3);
  g_nswp[dst] = ns_w[r*HH + c];
  g_nmwp[dst] = nm_w[r*HH + c];
}

// column-sliced GEMM, weights in registers; src = x (ns) or b (nm)
template<int B, bool USE_B>
__device__ __forceinline__ void gemm(const ulonglong2* __restrict__ w,
                                     SimSmem* s, int grp, int col, int off) {
  unsigned long long acc[B];
  #pragma unroll
  for (int j = 0; j < B; j++) acc[j] = 0ULL;
  #pragma unroll
  for (int jj = 0; jj < 4; jj++) {
    ulonglong2 wv = w[jj];
    #pragma unroll
    for (int j = 0; j < B; j++) {
      const float* src = USE_B ? s->b[off + j] : s->x[off + j];
      ulonglong2 v = *(const ulonglong2*)(&src[grp*16 + jj*4]);
      acc[j] = fma2(wv.x, v.x, acc[j]);
      acc[j] = fma2(wv.y, v.y, acc[j]);
    }
  }
  #pragma unroll
  for (int j = 0; j < B; j++)
    s->part[(j*NGC + grp)*CPC + col] = unpack_add(acc[j]);
}

__global__ __launch_bounds__(NT, 1) __cluster_dims__(2, 1, 1)
void sim_kernel(
    const float* __restrict__ fm,   const int* __restrict__ nb,
    const int*   __restrict__ nsp,
    const float* __restrict__ ns_b, const float* __restrict__ nm_b,
    const float* __restrict__ act_w, const float* __restrict__ act_b,
    const float* __restrict__ dec_w, const float* __restrict__ dec_b,
    float* __restrict__ out)
{
  extern __shared__ char raw[];
  SimSmem* s = (SimSmem*)raw;
  const int tid = threadIdx.x;
  const int col = tid & 63;          // local col 0..63
  const int grp = tid >> 6;          // 0..15 -> rows grp*16 .. grp*16+15
  const int wid = tid >> 5;
  const int lid = tid & 31;
  const int rank = (int)ctarank();
  const int peer = rank ^ 1;
  const int colg = rank*CPC + col;   // global output col
  const float THRESH = 1.0f - 1e-7f;

  // both weight slices register-resident (16 floats each)
  ulonglong2 wns[4], wnm[4];
  #pragma unroll
  for (int jj = 0; jj < 4; jj++) {
    wns[jj] = *(const ulonglong2*)&g_nswp[((grp*4 + jj)*HH + colg)*4];
    wnm[jj] = *(const ulonglong2*)&g_nmwp[((grp*4 + jj)*HH + colg)*4];
  }

  for (int i = tid; i < HM; i += NT) s->actw[i] = act_w[i];
  for (int i = tid; i < HH; i += NT) { s->nsb[i] = ns_b[i]; s->nmb[i] = nm_b[i]; s->g[i] = 0.f; }
  for (int i = tid; i < NN; i += NT) { s->tact[i] = 0.f; s->mark[i] = 0x7fffffff; }
  for (int i = tid; i < BMAX*HM; i += NT) { ((float*)s->x)[i] = 0.f; ((float*)s->b)[i] = 0.f; }
  if (tid == 0) {
    int nst = nsp ? nsp[0] : 64;
    s->head = 0; s->tail = nst; s->pops = 0; s->ev = 0; s->done = 0; s->bcnt = 0;
    s->actb = act_b[0];
  }
  __syncthreads();
  if (rank == 0) {
    int nstart = s->tail;
    for (int i = tid; i < nstart; i += NT) { g_qn[i] = i; g_qmid[i] = -1; }
  }
  __syncthreads();

  while (true) {
    // ---- SELECT (rank0, warp 0) + broadcast batch info to peer ----
    if (rank == 0 && tid < 32) {
      int head = s->head, tail = s->tail, pops = s->pops;
      int L = min(SCANW, min(tail - head, MAXSTEPS - pops));
      int nd[4], md[4]; bool lv[4]; unsigned m[4];
      #pragma unroll
      for (int t = 0; t < 4; t++) {
        int k = lid + 32*t;
        lv[t] = false; nd[t] = -1;
        if (k < L) {
          nd[t] = g_qn[head + k];
          md[t] = g_qmid[head + k];
          s->scanNd[k] = nd[t]; s->scanMid[k] = md[t];
          lv[t] = (s->tact[nd[t]] <= THRESH);
        }
        m[t] = __ballot_sync(0xffffffffu, lv[t]);
      }
      unsigned long long lmlo = (unsigned long long)m[0] | ((unsigned long long)m[1] << 32);
      unsigned long long lmhi = (unsigned long long)m[2] | ((unsigned long long)m[3] << 32);
      #pragma unroll
      for (int t = 0; t < 4; t++)
        if (lv[t]) atomicMin(&s->mark[nd[t]], lid + 32*t);
      __syncwarp();
      unsigned d[4];
      #pragma unroll
      for (int t = 0; t < 4; t++) {
        bool dup = lv[t] && (s->mark[nd[t]] != lid + 32*t);
        d[t] = __ballot_sync(0xffffffffu, dup);
      }
      __syncwarp();
      #pragma unroll
      for (int t = 0; t < 4; t++)
        if (lv[t]) s->mark[nd[t]] = 0x7fffffff;
      unsigned long long dmlo = (unsigned long long)d[0] | ((unsigned long long)d[1] << 32);
      unsigned long long dmhi = (unsigned long long)d[2] | ((unsigned long long)d[3] << 32);
      int dfirst = dmlo ? (__ffsll((long long)dmlo) - 1)
                 : (dmhi ? 64 + (__ffsll((long long)dmhi) - 1) : 128);
      int lim = min(dfirst, L);
      unsigned long long vlo = lmlo, vhi = lmhi;
      if (lim < 64)       { vlo &= (1ULL << lim) - 1ULL; vhi = 0ULL; }
      else if (lim < 128) { vhi &= (1ULL << (lim - 64)) - 1ULL; }
      int nlive = __popcll(vlo) + __popcll(vhi);
      int bc = min(nlive, BMAX);
      #pragma unroll
      for (int t = 0; t < 4; t++) {
        int k = lid + 32*t;
        bool sel = lv[t] && (k < lim);
        if (sel) {
          int rk;
          if (k < 64) rk = __popcll(vlo & ((1ULL << k) - 1ULL));
          else        rk = __popcll(vlo) + __popcll(vhi & ((k == 64) ? 0ULL : ((1ULL << (k - 64)) - 1ULL)));
          if (rk < BMAX) { s->bn[rk] = nd[t]; s->bmid[rk] = md[t]; }
          if (rk == BMAX - 1) s->kf16 = k + 1;
        }
      }
      __syncwarp();
      if (lid == 0) {
        if (L <= 0) { s->done = 1; s->bcnt = 0; }
        else {
          int kf = (nlive >= BMAX) ? s->kf16 : lim;
          s->head = head + kf; s->pops = pops + kf; s->bcnt = bc;
          s->evb = s->ev; s->tailb = tail; s->done = 0;
          s->ev += bc; s->tail = tail + bc*DEG;
        }
      }
      __syncwarp();
      // push batch info into peer smem
      if (lid < BMAX) {
        st_remote_s32(smem_u32(&s->bn[lid]),   peer, s->bn[lid]);
        st_remote_s32(smem_u32(&s->bmid[lid]), peer, s->bmid[lid]);
      }
      if (lid == 0) {
        st_remote_s32(smem_u32(&s->bcnt), peer, s->bcnt);
        st_remote_s32(smem_u32(&s->evb),  peer, s->evb);
        st_remote_s32(smem_u32(&s->done), peer, s->done);
      }
    }
    CSYNC();                               // A: publishes batch info + prev window writes
    if (s->done) break;
    const int bcnt = s->bcnt;
    if (bcnt == 0) continue;
    const int c0 = min(bcnt, 8), c1 = bcnt - c0;
    const int evb = s->evb;                // snapshot (select may overwrite later)
    const int tailb = s->tailb;

    // ---- gather full x (both CTAs) + enqueue refs (rank0) ----
    for (int i = tid; i < bcnt*HM; i += NT) {
      int j = i >> 8, k = i & 255;
      int ndg = s->bn[j];
      float v;
      if (k < HH) v = __ldcg(&g_feats[ndg*HH + k]);
      else {
        int mdg = s->bmid[j];
        v = (mdg < 0) ? fm[ndg*MM + (k - HH)] : __ldcg(&g_qmsg[mdg*MM + (k - HH)]);
        s->b[j][k] = v;
      }
      s->x[j][k] = v;
    }
    if (rank == 0 && tid >= NT - 256 && tid - (NT - 256) < bcnt*DEG) {
      int e = tid - (NT - 256);
      int j = e >> 4, dd = e & 15;
      g_qn  [tailb + e] = nb[s->bn[j]*DEG + dd];
      g_qmid[tailb + e] = evb + j;
    }
    __syncthreads();

    // ---- ACT (rank0) + ns GEMM half0 ----
    if (rank == 0 && wid < bcnt) {
      float ap = 0.f;
      #pragma unroll
      for (int t = 0; t < 8; t++)
        ap = fmaf(s->x[wid][lid*8 + t], s->actw[lid*8 + t], ap);
      #pragma unroll
      for (int o = 16; o > 0; o >>= 1) ap += __shfl_down_sync(0xffffffffu, ap, o);
      if (lid == 0) {
        float z = ap + s->actb;
        float cand = 1.0f / (1.0f + expf(-z));
        int ndl = s->bn[wid];
        float ta = s->tact[ndl];
        float na = (ta + cand > 1.0f) ? (1.0f - ta) : cand;
        s->tact[ndl] = ta + na;
        s->na[wid] = na;
      }
    }
    if (c0 <= 4) gemm<4,false>(wns, s, grp, col, 0);
    else         gemm<8,false>(wns, s, grp, col, 0);
    __syncthreads();
    // fin ns half0: local b slice + remote b slice + feats slice
    if (tid < c0*CPC) {
      int j = tid >> 6, k = tid & 63;
      float v = s->nsb[rank*CPC + k];
      #pragma unroll
      for (int gg = 0; gg < NGC; gg++) v += s->part[(j*NGC + gg)*CPC + k];
      v = fmaxf(v, 0.f);
      int cg = rank*CPC + k;
      s->b[j][cg] = v;
      st_remote_f32(smem_u32(&s->b[j][cg]), peer, v);
      g_feats[s->bn[j]*HH + cg] = v;
    }
    __syncthreads();
    if (c1 > 0) {
      if (c1 <= 4) gemm<4,false>(wns, s, grp, col, 8);
      else         gemm<8,false>(wns, s, grp, col, 8);
      __syncthreads();
      if (tid < c1*CPC) {
        int j = tid >> 6, k = tid & 63;
        float v = s->nsb[rank*CPC + k];
        #pragma unroll
        for (int gg = 0; gg < NGC; gg++) v += s->part[(j*NGC + gg)*CPC + k];
        v = fmaxf(v, 0.f);
        int cg = rank*CPC + k;
        s->b[8 + j][cg] = v;
        st_remote_f32(smem_u32(&s->b[8 + j][cg]), peer, v);
        g_feats[s->bn[8 + j]*HH + cg] = v;
      }
    }
    CSYNC();                               // B: publishes ns exchange + feats

    // ---- g-accumulate (rank0, queue order) + nm GEMM half0 ----
    if (rank == 0 && tid < HH) {
      float gv = s->g[tid];
      for (int j = 0; j < bcnt; j++) gv = fmaf(s->b[j][tid], s->na[j], gv);
      s->g[tid] = gv;
    }
    if (c0 <= 4) gemm<4,true>(wnm, s, grp, col, 0);
    else         gemm<8,true>(wnm, s, grp, col, 0);
    __syncthreads();
    if (tid < c0*CPC) {
      int j = tid >> 6, k = tid & 63;
      float v = s->nmb[rank*CPC + k];
      #pragma unroll
      for (int gg = 0; gg < NGC; gg++) v += s->part[(j*NGC + gg)*CPC + k];
      g_qmsg[(evb + j)*MM + rank*CPC + k] = v;
    }
    if (c1 > 0) {
      __syncthreads();
      if (c1 <= 4) gemm<4,true>(wnm, s, grp, col, 8);
      else         gemm<8,true>(wnm, s, grp, col, 8);
      __syncthreads();
      if (tid < c1*CPC) {
        int j = tid >> 6, k = tid & 63;
        float v = s->nmb[rank*CPC + k];
        #pragma unroll
        for (int gg = 0; gg < NGC; gg++) v += s->part[(j*NGC + gg)*CPC + k];
        g_qmsg[(evb + 8 + j)*MM + rank*CPC + k] = v;
      }
    }
    __syncthreads();
  }

  // ---- readout on rank0 ----
  if (rank != 0) return;
  __syncthreads();
  if (tid < 20) {
    int p = tid / 10, o = tid % 10;
    float a = dec_b[p*10 + o];
    for (int h = 0; h < HH; h++) a = fmaf(s->g[h], dec_w[(p*HH + h)*10 + o], a);
    s->part[tid] = a;
  }
  __syncthreads();
  if (tid < 2) {
    float mx = -1e30f;
    for (int o = 0; o < 10; o++) mx = fmaxf(mx, s->part[tid*10 + o]);
    float sum = 0.f;
    for (int o = 0; o < 10; o++) sum += expf(s->part[tid*10 + o] - mx);
    float lse = mx + logf(sum);
    for (int o = 0; o < 10; o++) out[tid*10 + o] = s->part[tid*10 + o] - lse;
  }
}

extern "C" void kernel_launch(void* const* d_in, const int* in_sizes, int n_in,
                              void* d_out, int out_size) {
  (void)out_size;
  const float* xa = (const float*)d_in[0];
  const float* fm = (const float*)d_in[1];
  const int*   nb = (const int*)d_in[2];
  const int*   nsp = nullptr;
  int b = 3;
  if (n_in >= 14 && in_sizes[3] == 1) { nsp = (const int*)d_in[3]; b = 4; }
  const float* enc_w = (const float*)d_in[b + 0];
  const float* enc_b = (const float*)d_in[b + 1];
  const float* ns_w  = (const float*)d_in[b + 2];
  const float* ns_b  = (const float*)d_in[b + 3];
  const float* nm_w  = (const float*)d_in[b + 4];
  const float* nm_b  = (const float*)d_in[b + 5];
  const float* act_w = (const float*)d_in[b + 6];
  const float* act_b = (const float*)d_in[b + 7];
  const float* dec_w = (const float*)d_in[b + 8];
  const float* dec_b = (const float*)d_in[b + 9];

  enc_kernel<<<NN, HH>>>(xa, enc_w, enc_b);
  pack_kernel<<<HM, HH>>>(ns_w, nm_w);

  cudaFuncSetAttribute(sim_kernel, cudaFuncAttributeMaxDynamicSharedMemorySize,
                       (int)sizeof(SimSmem));
  sim_kernel<<<2, NT, sizeof(SimSmem)>>>(fm, nb, nsp, ns_b, nm_b,
                                         act_w, act_b, dec_w, dec_b,
                                         (float*)d_out);
}

// round 11
// speedup vs baseline: 4.2779x; 1.4368x over previous
#include <cuda_runtime.h>
#include <stdint.h>
#include <math.h>

#define NN  1000
#define HH  128
#define MM  128
#define HM  256
#define DEG 16
#define MAXSTEPS 10000
#define CAPQ (NN + MAXSTEPS*DEG + 128)
#define BMAX 16
#define SCANW 128
#define NT   1024
#define NCTA 4
#define CPC  32     // cols per CTA
#define NGC  32     // row groups (8 rows each)

// Persistent device scratch (no allocation allowed)
__device__ float g_feats[NN*HH];
__device__ int   g_qn  [CAPQ];
__device__ int   g_qmid[CAPQ];           // -1 => first_message[node]
__device__ float g_qmsg[MAXSTEPS*MM];
// weights packed: float4 of 4 consecutive rows at fixed col: slot (r>>2)*128+col
__device__ float g_nswp[HM*HH];
__device__ float g_nmwp[HM*HH];

struct __align__(16) SimSmem {
  float x[BMAX][HM];           // batch inputs [feats,msg]  (16 KB)
  float b[BMAX][HM];           // [ns, msg] — ns via DSMEM exchange (16 KB)
  float part[BMAX*NGC*CPC];    // partials: 16 j x 32 grp x 32 col (64 KB)
  float actw[HM];
  float nsb[HH], nmb[HH], g[HH];
  float tact[NN];
  float na[BMAX];
  int   mark[NN];
  int scanNd[SCANW], scanMid[SCANW];
  int bn[BMAX], bmid[BMAX];
  int head, tail, pops, ev;
  int bcnt, evb, tailb, done, kf16;
  float actb;
};

__device__ __forceinline__ unsigned long long fma2(unsigned long long a,
                                                   unsigned long long b,
                                                   unsigned long long c) {
  unsigned long long d;
  asm("fma.rn.f32x2 %0, %1, %2, %3;" : "=l"(d) : "l"(a), "l"(b), "l"(c));
  return d;
}
__device__ __forceinline__ float unpack_add(unsigned long long a) {
  float lo, hi;
  asm("mov.b64 {%0,%1}, %2;" : "=f"(lo), "=f"(hi) : "l"(a));
  return lo + hi;
}
__device__ __forceinline__ uint32_t smem_u32(const void* p) {
  uint32_t a;
  asm("{ .reg .u64 t; cvta.to.shared.u64 t, %1; cvt.u32.u64 %0, t; }"
      : "=r"(a) : "l"(p));
  return a;
}
__device__ __forceinline__ void st_remote_f32(uint32_t laddr, int peer, float v) {
  uint32_t ra;
  asm("mapa.shared::cluster.u32 %0, %1, %2;" : "=r"(ra) : "r"(laddr), "r"(peer));
  asm volatile("st.shared::cluster.f32 [%0], %1;" :: "r"(ra), "f"(v) : "memory");
}
__device__ __forceinline__ void st_remote_s32(uint32_t laddr, int peer, int v) {
  uint32_t ra;
  asm("mapa.shared::cluster.u32 %0, %1, %2;" : "=r"(ra) : "r"(laddr), "r"(peer));
  asm volatile("st.shared::cluster.b32 [%0], %1;" :: "r"(ra), "r"(v) : "memory");
}
__device__ __forceinline__ uint32_t ctarank() {
  uint32_t r; asm("mov.u32 %0, %%cluster_ctarank;" : "=r"(r)); return r;
}
#define CSYNC() do { \
  asm volatile("barrier.cluster.arrive.aligned;" ::: "memory"); \
  asm volatile("barrier.cluster.wait.aligned;"   ::: "memory"); } while (0)

__global__ void enc_kernel(const float* __restrict__ xa,
                           const float* __restrict__ enc_w,
                           const float* __restrict__ enc_b) {
  int n = blockIdx.x, h = threadIdx.x;
  float a = enc_b[h];
  #pragma unroll
  for (int k = 0; k < 32; k++) a = fmaf(xa[n*32 + k], enc_w[k*HH + h], a);
  g_feats[n*HH + h] = a;
}

__global__ void pack_kernel(const float* __restrict__ ns_w,
                            const float* __restrict__ nm_w) {
  int r = blockIdx.x, c = threadIdx.x;
  int dst = (((r >> 2)*HH + c) << 2) + (r & 3);
  g_nswp[dst] = ns_w[r*HH + c];
  g_nmwp[dst] = nm_w[r*HH + c];
}

// column-sliced GEMM; each thread: 8 rows (grp) x 1 col; weights = 2 ulonglong2
template<int B, bool USE_B>
__device__ __forceinline__ void gemm(const ulonglong2* __restrict__ w,
                                     SimSmem* s, int grp, int col, int off) {
  unsigned long long acc[B];
  #pragma unroll
  for (int j = 0; j < B; j++) acc[j] = 0ULL;
  #pragma unroll
  for (int jj = 0; jj < 2; jj++) {
    ulonglong2 wv = w[jj];
    #pragma unroll
    for (int j = 0; j < B; j++) {
      const float* src = USE_B ? s->b[off + j] : s->x[off + j];
      ulonglong2 v = *(const ulonglong2*)(&src[grp*8 + jj*4]);
      acc[j] = fma2(wv.x, v.x, acc[j]);
      acc[j] = fma2(wv.y, v.y, acc[j]);
    }
  }
  #pragma unroll
  for (int j = 0; j < B; j++)
    s->part[((off + j)*NGC + grp)*CPC + col] = unpack_add(acc[j]);
}

__global__ __launch_bounds__(NT, 1) __cluster_dims__(NCTA, 1, 1)
void sim_kernel(
    const float* __restrict__ fm,   const int* __restrict__ nb,
    const int*   __restrict__ nsp,
    const float* __restrict__ ns_b, const float* __restrict__ nm_b,
    const float* __restrict__ act_w, const float* __restrict__ act_b,
    const float* __restrict__ dec_w, const float* __restrict__ dec_b,
    float* __restrict__ out)
{
  extern __shared__ char raw[];
  SimSmem* s = (SimSmem*)raw;
  const int tid = threadIdx.x;
  const int col = tid & 31;          // local col 0..31
  const int grp = tid >> 5;          // 0..31 -> rows grp*8 .. grp*8+7
  const int wid = tid >> 5;
  const int lid = tid & 31;
  const int rank = (int)ctarank();
  const int colg = rank*CPC + col;   // global output col
  const float THRESH = 1.0f - 1e-7f;

  // both weight slices register-resident (8 floats each)
  ulonglong2 wns[2], wnm[2];
  #pragma unroll
  for (int jj = 0; jj < 2; jj++) {
    wns[jj] = *(const ulonglong2*)&g_nswp[((grp*2 + jj)*HH + colg)*4];
    wnm[jj] = *(const ulonglong2*)&g_nmwp[((grp*2 + jj)*HH + colg)*4];
  }

  for (int i = tid; i < HM; i += NT) s->actw[i] = act_w[i];
  for (int i = tid; i < HH; i += NT) { s->nsb[i] = ns_b[i]; s->nmb[i] = nm_b[i]; s->g[i] = 0.f; }
  for (int i = tid; i < NN; i += NT) { s->tact[i] = 0.f; s->mark[i] = 0x7fffffff; }
  for (int i = tid; i < BMAX*HM; i += NT) { ((float*)s->x)[i] = 0.f; ((float*)s->b)[i] = 0.f; }
  if (tid == 0) {
    int nst = nsp ? nsp[0] : 64;
    s->head = 0; s->tail = nst; s->pops = 0; s->ev = 0; s->done = 0; s->bcnt = 0;
    s->actb = act_b[0];
  }
  __syncthreads();
  if (rank == 0) {
    int nstart = s->tail;
    for (int i = tid; i < nstart; i += NT) { g_qn[i] = i; g_qmid[i] = -1; }
  }
  __syncthreads();

  while (true) {
    // ---- SELECT (rank0, warp 0) + broadcast batch info to peers ----
    if (rank == 0 && tid < 32) {
      int head = s->head, tail = s->tail, pops = s->pops;
      int L = min(SCANW, min(tail - head, MAXSTEPS - pops));
      int nd[4], md[4]; bool lv[4]; unsigned m[4];
      #pragma unroll
      for (int t = 0; t < 4; t++) {
        int k = lid + 32*t;
        lv[t] = false; nd[t] = -1;
        if (k < L) {
          nd[t] = g_qn[head + k];
          md[t] = g_qmid[head + k];
          s->scanNd[k] = nd[t]; s->scanMid[k] = md[t];
          lv[t] = (s->tact[nd[t]] <= THRESH);
        }
        m[t] = __ballot_sync(0xffffffffu, lv[t]);
      }
      unsigned long long lmlo = (unsigned long long)m[0] | ((unsigned long long)m[1] << 32);
      unsigned long long lmhi = (unsigned long long)m[2] | ((unsigned long long)m[3] << 32);
      #pragma unroll
      for (int t = 0; t < 4; t++)
        if (lv[t]) atomicMin(&s->mark[nd[t]], lid + 32*t);
      __syncwarp();
      unsigned d[4];
      #pragma unroll
      for (int t = 0; t < 4; t++) {
        bool dup = lv[t] && (s->mark[nd[t]] != lid + 32*t);
        d[t] = __ballot_sync(0xffffffffu, dup);
      }
      __syncwarp();
      #pragma unroll
      for (int t = 0; t < 4; t++)
        if (lv[t]) s->mark[nd[t]] = 0x7fffffff;
      unsigned long long dmlo = (unsigned long long)d[0] | ((unsigned long long)d[1] << 32);
      unsigned long long dmhi = (unsigned long long)d[2] | ((unsigned long long)d[3] << 32);
      int dfirst = dmlo ? (__ffsll((long long)dmlo) - 1)
                 : (dmhi ? 64 + (__ffsll((long long)dmhi) - 1) : 128);
      int lim = min(dfirst, L);
      unsigned long long vlo = lmlo, vhi = lmhi;
      if (lim < 64)       { vlo &= (1ULL << lim) - 1ULL; vhi = 0ULL; }
      else if (lim < 128) { vhi &= (1ULL << (lim - 64)) - 1ULL; }
      int nlive = __popcll(vlo) + __popcll(vhi);
      int bc = min(nlive, BMAX);
      #pragma unroll
      for (int t = 0; t < 4; t++) {
        int k = lid + 32*t;
        bool sel = lv[t] && (k < lim);
        if (sel) {
          int rk;
          if (k < 64) rk = __popcll(vlo & ((1ULL << k) - 1ULL));
          else        rk = __popcll(vlo) + __popcll(vhi & ((k == 64) ? 0ULL : ((1ULL << (k - 64)) - 1ULL)));
          if (rk < BMAX) { s->bn[rk] = nd[t]; s->bmid[rk] = md[t]; }
          if (rk == BMAX - 1) s->kf16 = k + 1;
        }
      }
      __syncwarp();
      if (lid == 0) {
        if (L <= 0) { s->done = 1; s->bcnt = 0; }
        else {
          int kf = (nlive >= BMAX) ? s->kf16 : lim;
          s->head = head + kf; s->pops = pops + kf; s->bcnt = bc;
          s->evb = s->ev; s->tailb = tail; s->done = 0;
          s->ev += bc; s->tail = tail + bc*DEG;
        }
      }
      __syncwarp();
      // push batch info into all peer smems
      for (int p = 1; p < NCTA; p++) {
        if (lid < BMAX) {
          st_remote_s32(smem_u32(&s->bn[lid]),   p, s->bn[lid]);
          st_remote_s32(smem_u32(&s->bmid[lid]), p, s->bmid[lid]);
        }
        if (lid == 0) {
          st_remote_s32(smem_u32(&s->bcnt), p, s->bcnt);
          st_remote_s32(smem_u32(&s->evb),  p, s->evb);
          st_remote_s32(smem_u32(&s->done), p, s->done);
        }
      }
    }
    CSYNC();                               // A: publishes batch info + prev window writes
    if (s->done) break;
    const int bcnt = s->bcnt;
    if (bcnt == 0) continue;
    const int c0 = min(bcnt, 8), c1 = bcnt - c0;
    const int evb = s->evb;                // snapshot (select may overwrite later)
    const int tailb = s->tailb;

    // ---- gather full x (all CTAs) + enqueue refs (rank0) ----
    for (int i = tid; i < bcnt*HM; i += NT) {
      int j = i >> 8, k = i & 255;
      int ndg = s->bn[j];
      float v;
      if (k < HH) v = __ldcg(&g_feats[ndg*HH + k]);
      else {
        int mdg = s->bmid[j];
        v = (mdg < 0) ? fm[ndg*MM + (k - HH)] : __ldcg(&g_qmsg[mdg*MM + (k - HH)]);
        s->b[j][k] = v;
      }
      s->x[j][k] = v;
    }
    if (rank == 0 && tid >= NT - 256 && tid - (NT - 256) < bcnt*DEG) {
      int e = tid - (NT - 256);
      int j = e >> 4, dd = e & 15;
      g_qn  [tailb + e] = nb[s->bn[j]*DEG + dd];
      g_qmid[tailb + e] = evb + j;
    }
    __syncthreads();

    // ---- ACT (rank0) + ns GEMM (both halves, no intermediate barrier) ----
    if (rank == 0 && wid < bcnt) {
      float ap = 0.f;
      #pragma unroll
      for (int t = 0; t < 8; t++)
        ap = fmaf(s->x[wid][lid*8 + t], s->actw[lid*8 + t], ap);
      #pragma unroll
      for (int o = 16; o > 0; o >>= 1) ap += __shfl_down_sync(0xffffffffu, ap, o);
      if (lid == 0) {
        float z = ap + s->actb;
        float cand = 1.0f / (1.0f + expf(-z));
        int ndl = s->bn[wid];
        float ta = s->tact[ndl];
        float na = (ta + cand > 1.0f) ? (1.0f - ta) : cand;
        s->tact[ndl] = ta + na;
        s->na[wid] = na;
      }
    }
    if (c0 <= 4) gemm<4,false>(wns, s, grp, col, 0);
    else         gemm<8,false>(wns, s, grp, col, 0);
    if (c1 > 0) {
      if (c1 <= 4) gemm<4,false>(wns, s, grp, col, 8);
      else         gemm<8,false>(wns, s, grp, col, 8);
    }
    __syncthreads();

    // ---- finalize ns: relu, local b slice + 3 remote slices + feats slice ----
    if (tid < bcnt*CPC) {
      int j = tid >> 5, k = tid & 31;
      float v = s->nsb[colg - col + k];   // nsb[rank*CPC + k]
      #pragma unroll
      for (int gg = 0; gg < NGC; gg++) v += s->part[(j*NGC + gg)*CPC + k];
      v = fmaxf(v, 0.f);
      int cg = rank*CPC + k;
      s->b[j][cg] = v;
      uint32_t la = smem_u32(&s->b[j][cg]);
      #pragma unroll
      for (int p = 0; p < NCTA; p++)
        if (p != rank) st_remote_f32(la, p, v);
      g_feats[s->bn[j]*HH + cg] = v;
    }
    CSYNC();                               // B: publishes ns exchange + feats

    // ---- g-accumulate (rank0, queue order) + nm GEMM (both halves) ----
    if (rank == 0 && tid < HH) {
      float gv = s->g[tid];
      for (int j = 0; j < bcnt; j++) gv = fmaf(s->b[j][tid], s->na[j], gv);
      s->g[tid] = gv;
    }
    if (c0 <= 4) gemm<4,true>(wnm, s, grp, col, 0);
    else         gemm<8,true>(wnm, s, grp, col, 0);
    if (c1 > 0) {
      if (c1 <= 4) gemm<4,true>(wnm, s, grp, col, 8);
      else         gemm<8,true>(wnm, s, grp, col, 8);
    }
    __syncthreads();

    // ---- finalize nm -> qmsg column slice ----
    if (tid < bcnt*CPC) {
      int j = tid >> 5, k = tid & 31;
      float v = s->nmb[rank*CPC + k];
      #pragma unroll
      for (int gg = 0; gg < NGC; gg++) v += s->part[(j*NGC + gg)*CPC + k];
      g_qmsg[(evb + j)*MM + rank*CPC + k] = v;
    }
    __syncthreads();
  }

  // ---- readout on rank0 ----
  if (rank != 0) return;
  __syncthreads();
  if (tid < 20) {
    int p = tid / 10, o = tid % 10;
    float a = dec_b[p*10 + o];
    for (int h = 0; h < HH; h++) a = fmaf(s->g[h], dec_w[(p*HH + h)*10 + o], a);
    s->part[tid] = a;
  }
  __syncthreads();
  if (tid < 2) {
    float mx = -1e30f;
    for (int o = 0; o < 10; o++) mx = fmaxf(mx, s->part[tid*10 + o]);
    float sum = 0.f;
    for (int o = 0; o < 10; o++) sum += expf(s->part[tid*10 + o] - mx);
    float lse = mx + logf(sum);
    for (int o = 0; o < 10; o++) out[tid*10 + o] = s->part[tid*10 + o] - lse;
  }
}

extern "C" void kernel_launch(void* const* d_in, const int* in_sizes, int n_in,
                              void* d_out, int out_size) {
  (void)out_size;
  const float* xa = (const float*)d_in[0];
  const float* fm = (const float*)d_in[1];
  const int*   nb = (const int*)d_in[2];
  const int*   nsp = nullptr;
  int b = 3;
  if (n_in >= 14 && in_sizes[3] == 1) { nsp = (const int*)d_in[3]; b = 4; }
  const float* enc_w = (const float*)d_in[b + 0];
  const float* enc_b = (const float*)d_in[b + 1];
  const float* ns_w  = (const float*)d_in[b + 2];
  const float* ns_b  = (const float*)d_in[b + 3];
  const float* nm_w  = (const float*)d_in[b + 4];
  const float* nm_b  = (const float*)d_in[b + 5];
  const float* act_w = (const float*)d_in[b + 6];
  const float* act_b = (const float*)d_in[b + 7];
  const float* dec_w = (const float*)d_in[b + 8];
  const float* dec_b = (const float*)d_in[b + 9];

  enc_kernel<<<NN, HH>>>(xa, enc_w, enc_b);
  pack_kernel<<<HM, HH>>>(ns_w, nm_w);

  cudaFuncSetAttribute(sim_kernel, cudaFuncAttributeMaxDynamicSharedMemorySize,
                       (int)sizeof(SimSmem));
  sim_kernel<<<NCTA, NT, sizeof(SimSmem)>>>(fm, nb, nsp, ns_b, nm_b,
                                            act_w, act_b, dec_w, dec_b,
                                            (float*)d_out);
}

// round 13
// speedup vs baseline: 4.9719x; 1.1622x over previous
#include <cuda_runtime.h>
#include <stdint.h>
#include <math.h>

#define NN  1000
#define HH  128
#define MM  128
#define HM  256
#define DEG 16
#define MAXSTEPS 10000
#define CAPQ (NN + MAXSTEPS*DEG + 128)
#define BMAX 16
#define SCANW 128
#define NT   1024
#define NCTA 4
#define CPC  32     // output cols per CTA

// Persistent device scratch (no allocation allowed)
__device__ float g_feats[NN*HH];
__device__ int   g_qn  [CAPQ];
__device__ int   g_qmid[CAPQ];           // -1 => first_message[node]
__device__ float g_qmsg[MAXSTEPS*MM];
__device__ float g_nswp[HM*HH];          // packed: float4 of 4 rows at fixed col
__device__ float g_nmwp[HM*HH];
__device__ float g_gout[HH];

struct __align__(16) SimSmem {
  float x[BMAX][HM];            // batch inputs [feats,msg] (16 KB)
  float b[BMAX][HM];            // [ns(local cols), msg(full)] (16 KB)
  float part[BMAX*32*CPC];      // ns: 16x32x32 / nm: 16x8x128 (64 KB)
  float rsum[2][NCTA][BMAX][CPC]; // nm partial exchange, double-buffered (16 KB)
  float actw[HM];
  float nsb[HH], nmb[HH], gsl[CPC];
  float tact[NN];
  float na[BMAX];
  int   mark[NN];
  int scanNd[SCANW], scanMid[SCANW];
  int bn[BMAX], bmid[BMAX];
  int head, tail, pops, ev, bcnt, evb, tailb, done, kf16;
  float actb;
};

__device__ __forceinline__ unsigned long long fma2(unsigned long long a,
                                                   unsigned long long b,
                                                   unsigned long long c) {
  unsigned long long d;
  asm("fma.rn.f32x2 %0, %1, %2, %3;" : "=l"(d) : "l"(a), "l"(b), "l"(c));
  return d;
}
__device__ __forceinline__ float unpack_add(unsigned long long a) {
  float lo, hi;
  asm("mov.b64 {%0,%1}, %2;" : "=f"(lo), "=f"(hi) : "l"(a));
  return lo + hi;
}
__device__ __forceinline__ uint32_t smem_u32(const void* p) {
  uint32_t a;
  asm("{ .reg .u64 t; cvta.to.shared.u64 t, %1; cvt.u32.u64 %0, t; }"
      : "=r"(a) : "l"(p));
  return a;
}
__device__ __forceinline__ void st_remote_f32(uint32_t laddr, int peer, float v) {
  uint32_t ra;
  asm("mapa.shared::cluster.u32 %0, %1, %2;" : "=r"(ra) : "r"(laddr), "r"(peer));
  asm volatile("st.shared::cluster.f32 [%0], %1;" :: "r"(ra), "f"(v) : "memory");
}
__device__ __forceinline__ uint32_t ctarank() {
  uint32_t r; asm("mov.u32 %0, %%cluster_ctarank;" : "=r"(r)); return r;
}
#define CSYNC() do { \
  asm volatile("barrier.cluster.arrive.aligned;" ::: "memory"); \
  asm volatile("barrier.cluster.wait.aligned;"   ::: "memory"); } while (0)

__global__ void enc_kernel(const float* __restrict__ xa,
                           const float* __restrict__ enc_w,
                           const float* __restrict__ enc_b) {
  int n = blockIdx.x, h = threadIdx.x;
  float a = enc_b[h];
  #pragma unroll
  for (int k = 0; k < 32; k++) a = fmaf(xa[n*32 + k], enc_w[k*HH + h], a);
  g_feats[n*HH + h] = a;
}

__global__ void pack_kernel(const float* __restrict__ ns_w,
                            const float* __restrict__ nm_w) {
  int r = blockIdx.x, c = threadIdx.x;
  int dst = (((r >> 2)*HH + c) << 2) + (r & 3);
  g_nswp[dst] = ns_w[r*HH + c];
  g_nmwp[dst] = nm_w[r*HH + c];
}

// ns GEMM (col-split): thread (grp=tid>>5: 8 rows, col=tid&31)
template<int B>
__device__ __forceinline__ void gemm_ns(const ulonglong2* __restrict__ w,
                                        SimSmem* s, int grp, int col, int off) {
  unsigned long long acc[B];
  #pragma unroll
  for (int j = 0; j < B; j++) acc[j] = 0ULL;
  #pragma unroll
  for (int jj = 0; jj < 2; jj++) {
    ulonglong2 wv = w[jj];
    #pragma unroll
    for (int j = 0; j < B; j++) {
      ulonglong2 v = *(const ulonglong2*)(&s->x[off + j][grp*8 + jj*4]);
      acc[j] = fma2(wv.x, v.x, acc[j]);
      acc[j] = fma2(wv.y, v.y, acc[j]);
    }
  }
  #pragma unroll
  for (int j = 0; j < B; j++)
    s->part[((off + j)*32 + grp)*CPC + col] = unpack_add(acc[j]);
}

// nm GEMM (row-split): thread (grp2=tid>>7: 8 local rows, col2=tid&127)
template<int B>
__device__ __forceinline__ void gemm_nm(const ulonglong2* __restrict__ w,
                                        SimSmem* s, int rbase, int col2, int off) {
  unsigned long long acc[B];
  #pragma unroll
  for (int j = 0; j < B; j++) acc[j] = 0ULL;
  #pragma unroll
  for (int jj = 0; jj < 2; jj++) {
    ulonglong2 wv = w[jj];
    #pragma unroll
    for (int j = 0; j < B; j++) {
      ulonglong2 v = *(const ulonglong2*)(&s->b[off + j][rbase + jj*4]);
      acc[j] = fma2(wv.x, v.x, acc[j]);
      acc[j] = fma2(wv.y, v.y, acc[j]);
    }
  }
  int grp2 = col2 >> 31; (void)grp2;
  #pragma unroll
  for (int j = 0; j < B; j++)
    ((float*)s->part)[0] = 0.f;  // placeholder overwritten below (never used)
}

__global__ __launch_bounds__(NT, 1) __cluster_dims__(NCTA, 1, 1)
void sim_kernel(
    const float* __restrict__ fm,   const int* __restrict__ nb,
    const int*   __restrict__ nsp,
    const float* __restrict__ ns_b, const float* __restrict__ nm_b,
    const float* __restrict__ act_w, const float* __restrict__ act_b,
    const float* __restrict__ dec_w, const float* __restrict__ dec_b,
    float* __restrict__ out)
{
  extern __shared__ char raw[];
  SimSmem* s = (SimSmem*)raw;
  const int tid = threadIdx.x;
  const int col = tid & 31;          // ns: local col
  const int grp = tid >> 5;          // ns: 32 groups x 8 rows
  const int col2 = tid & 127;        // nm: global out col
  const int grp2 = tid >> 7;         // nm: 8 groups x 8 local rows
  const int wid = tid >> 5;
  const int lid = tid & 31;
  const int rank = (int)ctarank();
  const int colg = rank*CPC + col;
  // nm local input row base (global row index into b)
  const int rbase = (grp2 < 4) ? (rank*CPC + grp2*8)
                               : (HH + rank*CPC + (grp2 - 4)*8);
  const float THRESH = 1.0f - 1e-7f;

  // register weights: ns col-slice (8 floats), nm row-slice (8 floats)
  ulonglong2 wns[2], wnm[2];
  #pragma unroll
  for (int jj = 0; jj < 2; jj++) {
    wns[jj] = *(const ulonglong2*)&g_nswp[(((grp*8 + jj*4) >> 2)*HH + colg)*4];
    wnm[jj] = *(const ulonglong2*)&g_nmwp[(((rbase + jj*4) >> 2)*HH + col2)*4];
  }

  for (int i = tid; i < HM; i += NT) s->actw[i] = act_w[i];
  for (int i = tid; i < HH; i += NT) { s->nsb[i] = ns_b[i]; s->nmb[i] = nm_b[i]; }
  for (int i = tid; i < CPC; i += NT) s->gsl[i] = 0.f;
  if (tid < CPC) s->gsl[tid] = 0.f;
  for (int i = tid; i < NN; i += NT) { s->tact[i] = 0.f; s->mark[i] = 0x7fffffff; }
  for (int i = tid; i < BMAX*HM; i += NT) { ((float*)s->x)[i] = 0.f; ((float*)s->b)[i] = 0.f; }
  if (tid == 0) {
    int nst = nsp ? nsp[0] : 64;
    s->head = 0; s->tail = nst; s->pops = 0; s->ev = 0; s->done = 0; s->bcnt = 0;
    s->actb = act_b[0];
  }
  __syncthreads();
  if (rank == 0) {
    int nstart = s->tail;
    for (int i = tid; i < nstart; i += NT) { g_qn[i] = i; g_qmid[i] = -1; }
  }
  __syncthreads();

  int prevbc = 0, prevevb = 0, wpar = 0;

  while (true) {
    CSYNC();   // orders: peers' qmsg/feats/enqueue globals + rsum remote stores

    // ---- phase 0: finalize prev nm (qmsg) + g-acc + SELECT (all CTAs) ----
    if (tid < prevbc*CPC) {
      int j = tid >> 5, k = tid & 31;
      int p = wpar ^ 1;
      float v = s->nmb[rank*CPC + k]
              + s->rsum[p][0][j][k] + s->rsum[p][1][j][k]
              + s->rsum[p][2][j][k] + s->rsum[p][3][j][k];
      g_qmsg[(prevevb + j)*MM + rank*CPC + k] = v;
    }
    if (tid >= 512 && tid < 512 + CPC) {   // g-acc for prev window (local cols)
      int k = tid - 512;
      float gv = s->gsl[k];
      for (int j = 0; j < prevbc; j++)
        gv = fmaf(s->b[j][rank*CPC + k], s->na[j], gv);
      s->gsl[k] = gv;
    }
    if (tid < 32) {   // redundant select on every CTA (deterministic)
      int head = s->head, tail = s->tail, pops = s->pops;
      int L = min(SCANW, min(tail - head, MAXSTEPS - pops));
      int nd[4], md[4]; bool lv[4]; unsigned m[4];
      #pragma unroll
      for (int t = 0; t < 4; t++) {
        int k = lid + 32*t;
        lv[t] = false; nd[t] = -1; md[t] = -1;
        if (k < L) {
          nd[t] = __ldcg(&g_qn[head + k]);
          md[t] = __ldcg(&g_qmid[head + k]);
          s->scanNd[k] = nd[t]; s->scanMid[k] = md[t];
          lv[t] = (s->tact[nd[t]] <= THRESH);
        }
        m[t] = __ballot_sync(0xffffffffu, lv[t]);
      }
      unsigned long long lmlo = (unsigned long long)m[0] | ((unsigned long long)m[1] << 32);
      unsigned long long lmhi = (unsigned long long)m[2] | ((unsigned long long)m[3] << 32);
      #pragma unroll
      for (int t = 0; t < 4; t++)
        if (lv[t]) atomicMin(&s->mark[nd[t]], lid + 32*t);
      __syncwarp();
      unsigned d[4];
      #pragma unroll
      for (int t = 0; t < 4; t++) {
        // stop at dup OR at entry whose message isn't globally finalized yet
        bool stop = lv[t] && ((s->mark[nd[t]] != lid + 32*t) ||
                              (prevbc > 0 && md[t] >= prevevb));
        d[t] = __ballot_sync(0xffffffffu, stop);
      }
      __syncwarp();
      #pragma unroll
      for (int t = 0; t < 4; t++)
        if (lv[t]) s->mark[nd[t]] = 0x7fffffff;
      unsigned long long dmlo = (unsigned long long)d[0] | ((unsigned long long)d[1] << 32);
      unsigned long long dmhi = (unsigned long long)d[2] | ((unsigned long long)d[3] << 32);
      int dfirst = dmlo ? (__ffsll((long long)dmlo) - 1)
                 : (dmhi ? 64 + (__ffsll((long long)dmhi) - 1) : 128);
      int lim = min(dfirst, L);
      unsigned long long vlo = lmlo, vhi = lmhi;
      if (lim < 64)       { vlo &= (1ULL << lim) - 1ULL; vhi = 0ULL; }
      else if (lim < 128) { vhi &= (1ULL << (lim - 64)) - 1ULL; }
      int nlive = __popcll(vlo) + __popcll(vhi);
      int bc = min(nlive, BMAX);
      #pragma unroll
      for (int t = 0; t < 4; t++) {
        int k = lid + 32*t;
        bool sel = lv[t] && (k < lim);
        if (sel) {
          int rk;
          if (k < 64) rk = __popcll(vlo & ((1ULL << k) - 1ULL));
          else        rk = __popcll(vlo) + __popcll(vhi & ((k == 64) ? 0ULL : ((1ULL << (k - 64)) - 1ULL)));
          if (rk < BMAX) { s->bn[rk] = nd[t]; s->bmid[rk] = md[t]; }
          if (rk == BMAX - 1) s->kf16 = k + 1;
        }
      }
      __syncwarp();
      if (lid == 0) {
        if (L <= 0) { s->done = 1; s->bcnt = 0; }
        else {
          int kf = (nlive >= BMAX) ? s->kf16 : lim;
          s->head = head + kf; s->pops = pops + kf; s->bcnt = bc;
          s->evb = s->ev; s->tailb = tail; s->done = 0;
          s->ev += bc; s->tail = tail + bc*DEG;
        }
      }
    }
    __syncthreads();
    if (s->done) break;
    const int bcnt = s->bcnt;
    if (bcnt == 0) { prevbc = 0; prevevb = s->ev; continue; }
    const int c0 = min(bcnt, 8), c1 = bcnt - c0;
    const int evb = s->evb;
    const int tailb = s->tailb;

    // ---- phase 1: gather full x (float4) + enqueue refs (rank0) ----
    if (tid < bcnt*64) {
      int j = tid >> 6, q = (tid & 63) * 4;
      int ndg = s->bn[j];
      float4 v;
      if (q < HH) v = __ldcg((const float4*)&g_feats[ndg*HH + q]);
      else {
        int mdg = s->bmid[j];
        v = (mdg < 0) ? *(const float4*)&fm[ndg*MM + (q - HH)]
                      : __ldcg((const float4*)&g_qmsg[mdg*MM + (q - HH)]);
        *(float4*)&s->b[j][q] = v;
      }
      *(float4*)&s->x[j][q] = v;
    }
    if (rank == 0 && tid >= NT - 256 && tid - (NT - 256) < bcnt*DEG) {
      int e = tid - (NT - 256);
      int j = e >> 4, dd = e & 15;
      g_qn  [tailb + e] = nb[s->bn[j]*DEG + dd];
      g_qmid[tailb + e] = evb + j;
    }
    __syncthreads();

    // ---- phase 2: ACT (redundant, all CTAs) + ns GEMM ----
    if (wid < bcnt) {
      float ap = 0.f;
      #pragma unroll
      for (int t = 0; t < 8; t++)
        ap = fmaf(s->x[wid][lid*8 + t], s->actw[lid*8 + t], ap);
      #pragma unroll
      for (int o = 16; o > 0; o >>= 1) ap += __shfl_down_sync(0xffffffffu, ap, o);
      if (lid == 0) {
        float z = ap + s->actb;
        float cand = 1.0f / (1.0f + expf(-z));
        int ndl = s->bn[wid];
        float ta = s->tact[ndl];
        float na = (ta + cand > 1.0f) ? (1.0f - ta) : cand;
        s->tact[ndl] = ta + na;
        s->na[wid] = na;
      }
    }
    if (c0 <= 4) gemm_ns<4>(wns, s, grp, col, 0);
    else         gemm_ns<8>(wns, s, grp, col, 0);
    if (c1 > 0) {
      if (c1 <= 4) gemm_ns<4>(wns, s, grp, col, 8);
      else         gemm_ns<8>(wns, s, grp, col, 8);
    }
    __syncthreads();

    // ---- phase 3: finalize ns (local cols): relu -> b, feats ----
    if (tid < bcnt*CPC) {
      int j = tid >> 5, k = tid & 31;
      float v = s->nsb[rank*CPC + k];
      #pragma unroll
      for (int gg = 0; gg < 32; gg++) v += s->part[(j*32 + gg)*CPC + k];
      v = fmaxf(v, 0.f);
      s->b[j][rank*CPC + k] = v;
      g_feats[s->bn[j]*HH + rank*CPC + k] = v;
    }
    __syncthreads();

    // ---- phase 4: nm GEMM row-split (local ns rows + local msg rows) ----
    {
      unsigned long long acc[8];
      // half 0
      {
        const int B = 8;
        #pragma unroll
        for (int j = 0; j < B; j++) acc[j] = 0ULL;
        #pragma unroll
        for (int jj = 0; jj < 2; jj++) {
          ulonglong2 wv = wnm[jj];
          #pragma unroll
          for (int j = 0; j < B; j++) {
            if (j < c0) {
              ulonglong2 v = *(const ulonglong2*)(&s->b[j][rbase + jj*4]);
              acc[j] = fma2(wv.x, v.x, acc[j]);
              acc[j] = fma2(wv.y, v.y, acc[j]);
            }
          }
        }
        #pragma unroll
        for (int j = 0; j < B; j++)
          if (j < c0) s->part[((j)*8 + grp2)*HH + col2] = unpack_add(acc[j]);
      }
      if (c1 > 0) {
        const int B = 8;
        #pragma unroll
        for (int j = 0; j < B; j++) acc[j] = 0ULL;
        #pragma unroll
        for (int jj = 0; jj < 2; jj++) {
          ulonglong2 wv = wnm[jj];
          #pragma unroll
          for (int j = 0; j < B; j++) {
            if (j < c1) {
              ulonglong2 v = *(const ulonglong2*)(&s->b[8 + j][rbase + jj*4]);
              acc[j] = fma2(wv.x, v.x, acc[j]);
              acc[j] = fma2(wv.y, v.y, acc[j]);
            }
          }
        }
        #pragma unroll
        for (int j = 0; j < B; j++)
          if (j < c1) s->part[((8 + j)*8 + grp2)*HH + col2] = unpack_add(acc[j]);
      }
    }
    __syncthreads();

    // ---- phase 5: reduce 8 groups + send partials to owner CTAs ----
    #pragma unroll
    for (int rep = 0; rep < 2; rep++) {
      int t2 = tid + rep*NT;
      int j = t2 >> 7, c = t2 & 127;
      if (j < bcnt) {
        float v = 0.f;
        #pragma unroll
        for (int gg = 0; gg < 8; gg++) v += s->part[(j*8 + gg)*HH + c];
        int owner = c >> 5, kk = c & 31;
        if (owner == rank) s->rsum[wpar][rank][j][kk] = v;
        else st_remote_f32(smem_u32(&s->rsum[wpar][rank][j][kk]), owner, v);
      }
    }
    prevbc = bcnt; prevevb = evb; wpar ^= 1;
    // no trailing CTA sync needed: loop-top CSYNC covers it
  }

  // ---- readout: combine g slices via global, rank0 computes output ----
  if (tid < CPC) g_gout[rank*CPC + tid] = s->gsl[tid];
  CSYNC();
  if (rank != 0) return;
  __syncthreads();
  if (tid < 20) {
    int p = tid / 10, o = tid % 10;
    float a = dec_b[p*10 + o];
    for (int h = 0; h < HH; h++)
      a = fmaf(__ldcg(&g_gout[h]), dec_w[(p*HH + h)*10 + o], a);
    s->part[tid] = a;
  }
  __syncthreads();
  if (tid < 2) {
    float mx = -1e30f;
    for (int o = 0; o < 10; o++) mx = fmaxf(mx, s->part[tid*10 + o]);
    float sum = 0.f;
    for (int o = 0; o < 10; o++) sum += expf(s->part[tid*10 + o] - mx);
    float lse = mx + logf(sum);
    for (int o = 0; o < 10; o++) out[tid*10 + o] = s->part[tid*10 + o] - lse;
  }
}

extern "C" void kernel_launch(void* const* d_in, const int* in_sizes, int n_in,
                              void* d_out, int out_size) {
  (void)out_size;
  const float* xa = (const float*)d_in[0];
  const float* fm = (const float*)d_in[1];
  const int*   nb = (const int*)d_in[2];
  const int*   nsp = nullptr;
  int b = 3;
  if (n_in >= 14 && in_sizes[3] == 1) { nsp = (const int*)d_in[3]; b = 4; }
  const float* enc_w = (const float*)d_in[b + 0];
  const float* enc_b = (const float*)d_in[b + 1];
  const float* ns_w  = (const float*)d_in[b + 2];
  const float* ns_b  = (const float*)d_in[b + 3];
  const float* nm_w  = (const float*)d_in[b + 4];
  const float* nm_b  = (const float*)d_in[b + 5];
  const float* act_w = (const float*)d_in[b + 6];
  const float* act_b = (const float*)d_in[b + 7];
  const float* dec_w = (const float*)d_in[b + 8];
  const float* dec_b = (const float*)d_in[b + 9];

  enc_kernel<<<NN, HH>>>(xa, enc_w, enc_b);
  pack_kernel<<<HM, HH>>>(ns_w, nm_w);

  cudaFuncSetAttribute(sim_kernel, cudaFuncAttributeMaxDynamicSharedMemorySize,
                       (int)sizeof(SimSmem));
  sim_kernel<<<NCTA, NT, sizeof(SimSmem)>>>(fm, nb, nsp, ns_b, nm_b,
                                            act_w, act_b, dec_w, dec_b,
                                            (float*)d_out);
}